// round 1
// baseline (speedup 1.0000x reference)
#include <cuda_runtime.h>

// Problem constants
#define Bn    8
#define CIN   256
#define COUT  256
#define Hdim  64
#define Wdim  64
#define NKv   11
#define TAPS  55      // effective kernel height = nk*5
#define KWv   5
#define CK    8       // input channels per K-chunk
#define CHT   64      // out channels per block
#define ROWS  2       // output rows per block
#define XCOLS 68      // W + 4 halo
#define XPAD  72      // padded smem stride

__device__ float g_sum[COUT];
__device__ float g_sqsum[COUT];

__global__ void zero_stats_kernel() {
    int t = threadIdx.x;
    if (t < COUT) { g_sum[t] = 0.f; g_sqsum[t] = 0.f; }
}

__global__ __launch_bounds__(256, 2)
void conv_fused_kernel(const float* __restrict__ x,
                       const float* __restrict__ w,
                       float* __restrict__ out)
{
    __shared__ float sx[ROWS][CK][XPAD];     // x rows with halo
    __shared__ float sw[CK][CHT * KWv];      // weights [ci][c*5+kw]

    const int tid = threadIdx.x;
    const int jg  = tid & 7;          // 8 groups x 8 cols
    const int cg  = (tid >> 3) & 15;  // 16 groups x 4 channels
    const int rg  = tid >> 7;         // 2 rows
    const int c0  = blockIdx.x * CHT;
    const int i0  = blockIdx.y * ROWS;
    const int b   = blockIdx.z;

    float acc[4][8];
#pragma unroll
    for (int c = 0; c < 4; ++c)
#pragma unroll
        for (int j = 0; j < 8; ++j) acc[c][j] = 0.f;

    const float* xb = x + (long)b * (CIN * Hdim * Wdim);

    for (int t = 0; t < TAPS; ++t) {
        const int idx = t / 5;
        const int kh  = t - idx * 5;
        const long wBase = ((long)c0 * NKv + idx) * (CIN * 25) + kh * 5;
        const int xr0 = i0 + t - 25;   // x row for out row i0 (rg=0)

        for (int cc = 0; cc < CIN; cc += CK) {
            __syncthreads();
            // ---- load x tile: ROWS*CK*XCOLS = 1088 floats ----
            for (int e = tid; e < ROWS * CK * XCOLS; e += 256) {
                int col = e % XCOLS;
                int q   = (e / XCOLS) & (CK - 1);
                int rr  = e / (XCOLS * CK);
                int xr  = xr0 + rr;
                int xc  = col - 2;
                float v = 0.f;
                if ((unsigned)xr < Hdim && (unsigned)xc < Wdim)
                    v = xb[((cc + q) * Hdim + xr) * Wdim + xc];
                sx[rr][q][col] = v;
            }
            // ---- load weights: CHT*CK*KW = 2560 floats ----
            for (int e = tid; e < CHT * CK * KWv; e += 256) {
                int kw = e % 5;
                int q  = (e / 5) & (CK - 1);
                int c  = e / (5 * CK);
                sw[q][c * 5 + kw] =
                    w[wBase + (long)c * (NKv * CIN * 25) + (cc + q) * 25 + kw];
            }
            __syncthreads();

            // ---- compute: 8 ci x (4ch x 8j x 5kw) FFMAs per thread ----
#pragma unroll
            for (int q = 0; q < CK; ++q) {
                float xv[12];
#pragma unroll
                for (int k = 0; k < 12; ++k) xv[k] = sx[rg][q][jg * 8 + k];
#pragma unroll
                for (int c = 0; c < 4; ++c) {
                    const float* wp = &sw[q][(cg * 4 + c) * 5];
                    const float w0 = wp[0], w1 = wp[1], w2 = wp[2],
                                w3 = wp[3], w4 = wp[4];
#pragma unroll
                    for (int j = 0; j < 8; ++j) {
                        float a = acc[c][j];
                        a += w0 * xv[j];
                        a += w1 * xv[j + 1];
                        a += w2 * xv[j + 2];
                        a += w3 * xv[j + 3];
                        a += w4 * xv[j + 4];
                        acc[c][j] = a;
                    }
                }
            }
        }
    }

    // ---- epilogue: store out0 + accumulate per-channel stats ----
    const int orow = i0 + rg;
#pragma unroll
    for (int c = 0; c < 4; ++c) {
        const int ch = c0 + cg * 4 + c;
        float* op = out + (((long)b * COUT + ch) * Hdim + orow) * Wdim + jg * 8;
        float s = 0.f, sq = 0.f;
#pragma unroll
        for (int j = 0; j < 8; ++j) { s += acc[c][j]; sq += acc[c][j] * acc[c][j]; }

        float4 v0 = make_float4(acc[c][0], acc[c][1], acc[c][2], acc[c][3]);
        float4 v1 = make_float4(acc[c][4], acc[c][5], acc[c][6], acc[c][7]);
        reinterpret_cast<float4*>(op)[0] = v0;
        reinterpret_cast<float4*>(op)[1] = v1;

        // warp reduction over the 8 jg lanes (low 3 lane bits) -> 8x fewer atomics
#pragma unroll
        for (int o = 1; o < 8; o <<= 1) {
            s  += __shfl_xor_sync(0xffffffffu, s,  o);
            sq += __shfl_xor_sync(0xffffffffu, sq, o);
        }
        if (jg == 0) {
            atomicAdd(&g_sum[ch], s);
            atomicAdd(&g_sqsum[ch], sq);
        }
    }
}

__global__ void bn_kernel(float* __restrict__ out,
                          const float* __restrict__ gamma,
                          const float* __restrict__ beta)
{
    const long total4 = (long)Bn * COUT * Hdim * Wdim / 4;
    long i4 = (long)blockIdx.x * blockDim.x + threadIdx.x;
    if (i4 >= total4) return;
    int c = (int)(i4 >> 10) & (COUT - 1);   // (i4*4)/(H*W) % COUT, H*W=4096
    const float invN = 1.0f / (float)(Bn * Hdim * Wdim);
    float mean  = g_sum[c] * invN;
    float var   = g_sqsum[c] * invN - mean * mean;
    float scale = gamma[c] * rsqrtf(var + 1e-5f);
    float shift = beta[c] - mean * scale;
    float4 v = reinterpret_cast<float4*>(out)[i4];
    v.x = v.x * scale + shift;
    v.y = v.y * scale + shift;
    v.z = v.z * scale + shift;
    v.w = v.w * scale + shift;
    reinterpret_cast<float4*>(out)[i4] = v;
}

extern "C" void kernel_launch(void* const* d_in, const int* in_sizes, int n_in,
                              void* d_out, int out_size)
{
    const float* x     = (const float*)d_in[0];
    const float* w     = (const float*)d_in[1];
    const float* gamma = (const float*)d_in[2];
    const float* beta  = (const float*)d_in[3];
    float* out = (float*)d_out;

    zero_stats_kernel<<<1, 256>>>();

    dim3 grid(COUT / CHT, Hdim / ROWS, Bn);   // (4, 32, 8) = 1024 blocks
    conv_fused_kernel<<<grid, 256>>>(x, w, out);

    const long total4 = (long)Bn * COUT * Hdim * Wdim / 4;  // 2,097,152
    bn_kernel<<<(unsigned)((total4 + 255) / 256), 256>>>(out, gamma, beta);
}

// round 4
// speedup vs baseline: 2.8449x; 2.8449x over previous
#include <cuda_runtime.h>
#include <cuda_bf16.h>
#include <stdint.h>

// ---------------- problem constants ----------------
#define Bn    8
#define CINc  256
#define COUTc 256
#define Hdim  64
#define Wdim  64
#define HP    120      // padded rows (h' = h + 25 in [0,118))
#define WP    68       // padded cols (w' = w + 2 in [0,68))
#define NTAP  275      // 55 t * 5 kw
#define NSTEP 2200     // 275 taps * 8 ci-chunks of 32

// ---------------- smem ----------------
#define OFF_B        16384          // A: [128][128B] = 16KB, then B: [256][128B] = 32KB
#define STAGE_STRIDE 49152          // 48KB per stage
#define NSTAGE       4
#define SMEM_TOTAL   (STAGE_STRIDE * NSTAGE)   // 192KB

// ---------------- device scratch (static globals; no allocs) ----------------
__device__ __align__(256) __nv_bfloat16 g_xh[(size_t)Bn * HP * WP * CINc];
__device__ __align__(256) __nv_bfloat16 g_xl[(size_t)Bn * HP * WP * CINc];
__device__ __align__(256) __nv_bfloat16 g_wh[(size_t)NTAP * COUTc * CINc];
__device__ __align__(256) __nv_bfloat16 g_wl[(size_t)NTAP * COUTc * CINc];
__device__ float g_sum[COUTc];
__device__ float g_sqsum[COUTc];

// ---------------- PTX helpers (arch-generic: sm_80-era ops only) ----------------
__device__ __forceinline__ uint32_t smem_u32(const void* p) {
    uint32_t a;
    asm("{ .reg .u64 t; cvta.to.shared.u64 t, %1; cvt.u32.u64 %0, t; }"
        : "=r"(a) : "l"(p));
    return a;
}
__device__ __forceinline__ void cp16(uint32_t dst, const void* src) {
    asm volatile("cp.async.cg.shared.global [%0], [%1], 16;"
                 :: "r"(dst), "l"(src) : "memory");
}
#define CP_COMMIT() asm volatile("cp.async.commit_group;" ::: "memory")
#define CP_WAIT(n)  asm volatile("cp.async.wait_group %0;" :: "n"(n) : "memory")

__device__ __forceinline__ void ldsm4(uint32_t& r0, uint32_t& r1,
                                      uint32_t& r2, uint32_t& r3, uint32_t a) {
    asm volatile("ldmatrix.sync.aligned.m8n8.x4.shared.b16 {%0,%1,%2,%3}, [%4];"
                 : "=r"(r0), "=r"(r1), "=r"(r2), "=r"(r3) : "r"(a));
}
__device__ __forceinline__ void mma16816(float& d0, float& d1, float& d2, float& d3,
                                         uint32_t a0, uint32_t a1, uint32_t a2, uint32_t a3,
                                         uint32_t b0, uint32_t b1) {
    asm volatile("mma.sync.aligned.m16n8k16.row.col.f32.bf16.bf16.f32 "
                 "{%0,%1,%2,%3},{%4,%5,%6,%7},{%8,%9},{%0,%1,%2,%3};"
                 : "+f"(d0), "+f"(d1), "+f"(d2), "+f"(d3)
                 : "r"(a0), "r"(a1), "r"(a2), "r"(a3), "r"(b0), "r"(b1));
}

// ---------------- prep kernels ----------------
__global__ void prep_w_kernel(const float* __restrict__ w) {
    int idx = blockIdx.x * 256 + threadIdx.x;   // 275*256*256
    int ci  = idx & 255;
    int co  = (idx >> 8) & 255;
    int tap = idx >> 16;
    int t = tap / 5, kw = tap - 5 * t;
    int ik = t / 5,  kh = t - 5 * ik;
    float f = w[(((size_t)(co * 11 + ik) * 256 + ci) * 25) + kh * 5 + kw];
    __nv_bfloat16 hi = __float2bfloat16(f);
    __nv_bfloat16 lo = __float2bfloat16(f - __bfloat162float(hi));
    g_wh[idx] = hi;
    g_wl[idx] = lo;
}

__global__ void prep_x_kernel(const float* __restrict__ x) {
    int idx = blockIdx.x * 256 + threadIdx.x;   // 8*120*68*256
    int ci   = idx & 255;
    int rest = idx >> 8;
    int wp = rest % WP;
    int r2 = rest / WP;
    int hp = r2 % HP;
    int b  = r2 / HP;
    int h = hp - 25, wq = wp - 2;
    float v = 0.f;
    if ((unsigned)h < 64u && (unsigned)wq < 64u)
        v = x[(((size_t)(b * 256 + ci) * 64) + h) * 64 + wq];
    __nv_bfloat16 hi = __float2bfloat16(v);
    __nv_bfloat16 lo = __float2bfloat16(v - __bfloat162float(hi));
    g_xh[idx] = hi;
    g_xl[idx] = lo;
}

__global__ void zero_stats_kernel() {
    int t = threadIdx.x;
    if (t < COUTc) { g_sum[t] = 0.f; g_sqsum[t] = 0.f; }
}

// ---------------- main GEMM kernel ----------------
__global__ __launch_bounds__(512, 1)
void gemm_kernel(float* __restrict__ out)
{
    extern __shared__ __align__(1024) char smem[];
    const uint32_t sb = smem_u32(smem);

    const int tid  = threadIdx.x;
    const int w    = tid >> 5;
    const int l    = tid & 31;
    const int mbase = blockIdx.x * 128;
    const int nblk  = blockIdx.y;            // 128 n-tiles
    const int b     = nblk >> 4;
    const int i0    = (nblk & 15) * 4;       // 4 output rows per CTA

    // ---- copy geometry (per thread) ----
    const int cA  = tid & 7;                 // 16B chunk within 128B row
    const int rA0 = tid >> 3;                // 0..63
    const uint32_t swc = 16u * (uint32_t)(cA ^ (rA0 & 7));
    const __nv_bfloat16* srcW = (cA < 4) ? g_wh : g_wl;
    const __nv_bfloat16* srcX = (cA < 4) ? g_xh : g_xl;
    const size_t aoff0 = (size_t)(mbase + rA0) * 256 + (size_t)(cA & 3) * 8;
    const uint32_t adst = (uint32_t)rA0 * 128 + swc;
    size_t xoff[4];
    uint32_t bdst[4];
#pragma unroll
    for (int k = 0; k < 4; ++k) {
        xoff[k] = (size_t)b * (HP * WP * 256)
                + ((size_t)(i0 + k) * WP + rA0) * 256 + (size_t)(cA & 3) * 8;
        bdst[k] = OFF_B + (uint32_t)(k * 64 + rA0) * 128 + swc;
    }

    // ---- mma geometry (per warp/lane) ----
    const int mrow0 = (w >> 3) * 64;
    const int nrow0 = (w & 7) * 32;
    const uint32_t swz = (uint32_t)(l & 7);
    const uint32_t hl  = (uint32_t)(l >> 4);
    const uint32_t aLaneOff = (uint32_t)(mrow0 + (l & 15)) * 128;
    const uint32_t bLaneOff = (uint32_t)(nrow0 + (l & 7) + ((l >> 3) & 1) * 8) * 128;

    float acc[4][4][4];
#pragma unroll
    for (int mi = 0; mi < 4; ++mi)
#pragma unroll
        for (int nt = 0; nt < 4; ++nt)
#pragma unroll
            for (int r = 0; r < 4; ++r) acc[mi][nt][r] = 0.f;

    // load-side step counters (tap = 5*t + kw; step = tap*8 + kc)
    int tL = 0, kwL = 0, kcL = 0, tapL = 0;

    // ---- issue one stage ----
    auto issue = [&](uint32_t stg) {
        const size_t aoff = aoff0 + (size_t)tapL * 65536 + (size_t)kcL * 32;
        cp16(stg + adst,        srcW + aoff);
        cp16(stg + adst + 8192, srcW + aoff + 16384);
        const size_t xc = ((size_t)tL * WP + kwL) * 256 + (size_t)kcL * 32;
#pragma unroll
        for (int k = 0; k < 4; ++k)
            cp16(stg + bdst[k], srcX + xoff[k] + xc);
    };
    auto advance = [&]() {
        if (++kcL == 8) {
            kcL = 0; ++tapL;
            if (++kwL == 5) { kwL = 0; ++tL; }
        }
    };

    // prologue: stages 0..2
#pragma unroll
    for (int s = 0; s < NSTAGE - 1; ++s) {
        issue(sb + s * STAGE_STRIDE);
        CP_COMMIT();
        advance();
    }

    for (int s = 0; s < NSTEP; ++s) {
        CP_WAIT(2);
        __syncthreads();
        if (s + NSTAGE - 1 < NSTEP) {
            issue(sb + ((s + NSTAGE - 1) & (NSTAGE - 1)) * STAGE_STRIDE);
            advance();
        }
        CP_COMMIT();

        const uint32_t stgA = sb + (s & (NSTAGE - 1)) * STAGE_STRIDE;
        const uint32_t stgB = stgA + OFF_B;

#pragma unroll
        for (int kh = 0; kh < 2; ++kh) {
            const uint32_t ch = 2u * kh + hl;        // hi chunk (0..3)
            const uint32_t cl = ch + 4u;             // lo chunk (4..7)
            uint32_t bh[8], bl[8];
            ldsm4(bh[0], bh[1], bh[2], bh[3], stgB + bLaneOff +    0 + 16u * (ch ^ swz));
            ldsm4(bh[4], bh[5], bh[6], bh[7], stgB + bLaneOff + 2048 + 16u * (ch ^ swz));
            ldsm4(bl[0], bl[1], bl[2], bl[3], stgB + bLaneOff +    0 + 16u * (cl ^ swz));
            ldsm4(bl[4], bl[5], bl[6], bl[7], stgB + bLaneOff + 2048 + 16u * (cl ^ swz));
            // Fragment pairing: ldsm4 register order is
            //   r0={n0-7,kLO} r1={n8-15,kLO} r2={n0-7,kHI} r3={n8-15,kHI}
            // mma {b0,b1} must be {kLO,kHI} of ONE n-group:
            //   nt=0 -> (bh[0],bh[2]); nt=1 -> (bh[1],bh[3]);
            //   nt=2 -> (bh[4],bh[6]); nt=3 -> (bh[5],bh[7]).
#pragma unroll
            for (int mi = 0; mi < 4; ++mi) {
                uint32_t ah[4], al[4];
                ldsm4(ah[0], ah[1], ah[2], ah[3],
                      stgA + aLaneOff + mi * 2048 + 16u * (ch ^ swz));
                ldsm4(al[0], al[1], al[2], al[3],
                      stgA + aLaneOff + mi * 2048 + 16u * (cl ^ swz));
#pragma unroll
                for (int nt = 0; nt < 4; ++nt) {
                    const int b0 = (nt & 1) + (nt >> 1) * 4;
                    const int b1 = b0 + 2;
                    mma16816(acc[mi][nt][0], acc[mi][nt][1], acc[mi][nt][2], acc[mi][nt][3],
                             ah[0], ah[1], ah[2], ah[3], bh[b0], bh[b1]);
                    mma16816(acc[mi][nt][0], acc[mi][nt][1], acc[mi][nt][2], acc[mi][nt][3],
                             al[0], al[1], al[2], al[3], bh[b0], bh[b1]);
                    mma16816(acc[mi][nt][0], acc[mi][nt][1], acc[mi][nt][2], acc[mi][nt][3],
                             ah[0], ah[1], ah[2], ah[3], bl[b0], bl[b1]);
                }
            }
        }
    }

    // ---- epilogue: stores + BN stats ----
    const int lg = l >> 2;          // acc row group within 16-row tile
    const int lc = l & 3;           // acc col group (2 cols each)
    const int orow = i0 + ((w & 7) >> 1);
    const int jb   = (w & 1) * 32;

#pragma unroll
    for (int mi = 0; mi < 4; ++mi) {
#pragma unroll
        for (int h = 0; h < 2; ++h) {
            const int m = mbase + mrow0 + mi * 16 + lg + h * 8;
            float* rowp = out + (((size_t)(b * 256 + m)) * 64 + orow) * 64 + jb + 2 * lc;
            float s = 0.f, sq = 0.f;
#pragma unroll
            for (int nt = 0; nt < 4; ++nt) {
                float c0 = acc[mi][nt][2 * h];
                float c1 = acc[mi][nt][2 * h + 1];
                reinterpret_cast<float2*>(rowp + nt * 8)[0] = make_float2(c0, c1);
                s  += c0 + c1;
                sq += c0 * c0 + c1 * c1;
            }
            s  += __shfl_xor_sync(0xffffffffu, s,  1);
            s  += __shfl_xor_sync(0xffffffffu, s,  2);
            sq += __shfl_xor_sync(0xffffffffu, sq, 1);
            sq += __shfl_xor_sync(0xffffffffu, sq, 2);
            if (lc == 0) {
                atomicAdd(&g_sum[m], s);
                atomicAdd(&g_sqsum[m], sq);
            }
        }
    }
}

// ---------------- BN normalize ----------------
__global__ void bn_kernel(float* __restrict__ out,
                          const float* __restrict__ gamma,
                          const float* __restrict__ beta)
{
    const long total4 = (long)Bn * COUTc * Hdim * Wdim / 4;
    long i4 = (long)blockIdx.x * blockDim.x + threadIdx.x;
    if (i4 >= total4) return;
    int c = (int)(i4 >> 10) & (COUTc - 1);
    const float invN = 1.0f / (float)(Bn * Hdim * Wdim);
    float mean  = g_sum[c] * invN;
    float var   = g_sqsum[c] * invN - mean * mean;
    float scale = gamma[c] * rsqrtf(var + 1e-5f);
    float shift = beta[c] - mean * scale;
    float4 v = reinterpret_cast<float4*>(out)[i4];
    v.x = v.x * scale + shift;
    v.y = v.y * scale + shift;
    v.z = v.z * scale + shift;
    v.w = v.w * scale + shift;
    reinterpret_cast<float4*>(out)[i4] = v;
}

// ---------------- launch ----------------
extern "C" void kernel_launch(void* const* d_in, const int* in_sizes, int n_in,
                              void* d_out, int out_size)
{
    const float* x     = (const float*)d_in[0];
    const float* w     = (const float*)d_in[1];
    const float* gamma = (const float*)d_in[2];
    const float* beta  = (const float*)d_in[3];
    float* out = (float*)d_out;

    cudaFuncSetAttribute(gemm_kernel, cudaFuncAttributeMaxDynamicSharedMemorySize,
                         SMEM_TOTAL);

    prep_w_kernel<<<70400, 256>>>(w);
    prep_x_kernel<<<65280, 256>>>(x);
    zero_stats_kernel<<<1, 256>>>();

    dim3 grid(2, 128);                     // 256 CTAs: 2 m-halves x (8 batch * 16 row-blocks)
    gemm_kernel<<<grid, 512, SMEM_TOTAL>>>(out);

    const long total4 = (long)Bn * COUTc * Hdim * Wdim / 4;
    bn_kernel<<<(unsigned)((total4 + 255) / 256), 256>>>(out, gamma, beta);
}

// round 5
// speedup vs baseline: 2.8692x; 1.0086x over previous
#include <cuda_runtime.h>
#include <cuda_bf16.h>
#include <stdint.h>

// ---------------- problem constants ----------------
#define Bn    8
#define CINc  256
#define COUTc 256
#define Hdim  64
#define Wdim  64
#define HP    120      // padded rows (h' = h + 25 in [0,118))
#define WP    68       // padded cols (w' = w + 2 in [0,68))
#define NTAP  275      // 55 t * 5 kw
#define NSTEP 2200     // 275 taps * 8 ci-chunks of 32

// ---------------- smem ----------------
#define OFF_B        16384          // A: [128][128B] = 16KB, then B: [256][128B] = 32KB
#define STAGE_STRIDE 49152          // 48KB per stage
#define NSTAGE       4
#define SMEM_TOTAL   (STAGE_STRIDE * NSTAGE)   // 192KB

// ---------------- device scratch (static globals; no allocs) ----------------
__device__ __align__(256) __nv_bfloat16 g_xh[(size_t)Bn * HP * WP * CINc];
__device__ __align__(256) __nv_bfloat16 g_xl[(size_t)Bn * HP * WP * CINc];
__device__ __align__(256) __nv_bfloat16 g_wh[(size_t)NTAP * COUTc * CINc];
__device__ __align__(256) __nv_bfloat16 g_wl[(size_t)NTAP * COUTc * CINc];
__device__ float g_sum[COUTc];
__device__ float g_sqsum[COUTc];

// ---------------- PTX helpers (arch-generic: sm_80-era ops only) ----------------
__device__ __forceinline__ uint32_t smem_u32(const void* p) {
    uint32_t a;
    asm("{ .reg .u64 t; cvta.to.shared.u64 t, %1; cvt.u32.u64 %0, t; }"
        : "=r"(a) : "l"(p));
    return a;
}
__device__ __forceinline__ void cp16(uint32_t dst, const void* src) {
    asm volatile("cp.async.cg.shared.global [%0], [%1], 16;"
                 :: "r"(dst), "l"(src) : "memory");
}
#define CP_COMMIT() asm volatile("cp.async.commit_group;" ::: "memory")
#define CP_WAIT(n)  asm volatile("cp.async.wait_group %0;" :: "n"(n) : "memory")

__device__ __forceinline__ void ldsm4(uint32_t& r0, uint32_t& r1,
                                      uint32_t& r2, uint32_t& r3, uint32_t a) {
    asm volatile("ldmatrix.sync.aligned.m8n8.x4.shared.b16 {%0,%1,%2,%3}, [%4];"
                 : "=r"(r0), "=r"(r1), "=r"(r2), "=r"(r3) : "r"(a));
}
__device__ __forceinline__ void mma16816(float& d0, float& d1, float& d2, float& d3,
                                         uint32_t a0, uint32_t a1, uint32_t a2, uint32_t a3,
                                         uint32_t b0, uint32_t b1) {
    asm volatile("mma.sync.aligned.m16n8k16.row.col.f32.bf16.bf16.f32 "
                 "{%0,%1,%2,%3},{%4,%5,%6,%7},{%8,%9},{%0,%1,%2,%3};"
                 : "+f"(d0), "+f"(d1), "+f"(d2), "+f"(d3)
                 : "r"(a0), "r"(a1), "r"(a2), "r"(a3), "r"(b0), "r"(b1));
}

// ---------------- prep kernels ----------------
__global__ void prep_w_kernel(const float* __restrict__ w) {
    int idx = blockIdx.x * 256 + threadIdx.x;   // 275*256*256
    int ci  = idx & 255;
    int co  = (idx >> 8) & 255;
    int tap = idx >> 16;
    int t = tap / 5, kw = tap - 5 * t;
    int ik = t / 5,  kh = t - 5 * ik;
    float f = w[(((size_t)(co * 11 + ik) * 256 + ci) * 25) + kh * 5 + kw];
    __nv_bfloat16 hi = __float2bfloat16(f);
    __nv_bfloat16 lo = __float2bfloat16(f - __bfloat162float(hi));
    g_wh[idx] = hi;
    g_wl[idx] = lo;
}

__global__ void prep_x_kernel(const float* __restrict__ x) {
    int idx = blockIdx.x * 256 + threadIdx.x;   // 8*120*68*256
    int ci   = idx & 255;
    int rest = idx >> 8;
    int wp = rest % WP;
    int r2 = rest / WP;
    int hp = r2 % HP;
    int b  = r2 / HP;
    int h = hp - 25, wq = wp - 2;
    float v = 0.f;
    if ((unsigned)h < 64u && (unsigned)wq < 64u)
        v = x[(((size_t)(b * 256 + ci) * 64) + h) * 64 + wq];
    __nv_bfloat16 hi = __float2bfloat16(v);
    __nv_bfloat16 lo = __float2bfloat16(v - __bfloat162float(hi));
    g_xh[idx] = hi;
    g_xl[idx] = lo;
}

__global__ void zero_stats_kernel() {
    int t = threadIdx.x;
    if (t < COUTc) { g_sum[t] = 0.f; g_sqsum[t] = 0.f; }
}

// ---------------- main GEMM kernel ----------------
__global__ __launch_bounds__(512, 1)
void gemm_kernel(float* __restrict__ out)
{
    extern __shared__ __align__(1024) char smem[];
    const uint32_t sb = smem_u32(smem);

    const int tid  = threadIdx.x;
    const int w    = tid >> 5;
    const int l    = tid & 31;
    const int mbase = blockIdx.x * 128;
    const int nblk  = blockIdx.y;            // 128 n-tiles
    const int b     = nblk >> 4;
    const int i0    = (nblk & 15) * 4;       // 4 output rows per CTA

    // ---- copy geometry (per thread) ----
    const int cA  = tid & 7;                 // 16B chunk within 128B row
    const int rA0 = tid >> 3;                // 0..63
    const uint32_t swc = 16u * (uint32_t)(cA ^ (rA0 & 7));
    const __nv_bfloat16* srcW = (cA < 4) ? g_wh : g_wl;
    const __nv_bfloat16* srcX = (cA < 4) ? g_xh : g_xl;
    const uint32_t adst = (uint32_t)rA0 * 128 + swc;
    uint32_t bdst[4];
#pragma unroll
    for (int k = 0; k < 4; ++k)
        bdst[k] = OFF_B + (uint32_t)(k * 64 + rA0) * 128 + swc;

    // incremental source pointers (element units; bf16)
    const __nv_bfloat16* aptr = srcW + (size_t)(mbase + rA0) * 256 + (size_t)(cA & 3) * 8;
    const __nv_bfloat16* xptr = srcX + (size_t)b * (HP * WP * 256)
                              + ((size_t)i0 * WP + rA0) * 256 + (size_t)(cA & 3) * 8;
    int ac8 = 0;     // A: every 8th issue jumps a tap
    int xc40 = 0;    // X: every 40th issue jumps a t-row

    // ---- mma geometry (per warp/lane) ----
    const int mrow0 = (w >> 3) * 64;
    const int nrow0 = (w & 7) * 32;
    const uint32_t swz = (uint32_t)(l & 7);
    const uint32_t hl  = (uint32_t)(l >> 4);
    const uint32_t aLaneOff = (uint32_t)(mrow0 + (l & 15)) * 128;
    const uint32_t bLaneOff = (uint32_t)(nrow0 + (l & 7) + ((l >> 3) & 1) * 8) * 128;

    float acc[4][4][4];
#pragma unroll
    for (int mi = 0; mi < 4; ++mi)
#pragma unroll
        for (int nt = 0; nt < 4; ++nt)
#pragma unroll
            for (int r = 0; r < 4; ++r) acc[mi][nt][r] = 0.f;

    // ---- issue one stage (incremental addressing) ----
    auto issue = [&](uint32_t stg) {
        cp16(stg + adst,        aptr);
        cp16(stg + adst + 8192, aptr + 16384);
#pragma unroll
        for (int k = 0; k < 4; ++k)
            cp16(stg + bdst[k], xptr + k * (WP * 256));
        aptr += (ac8 == 7) ? 65312 : 32;
        ac8 = (ac8 + 1) & 7;
        xptr += (xc40 == 39) ? 16160 : 32;
        xc40 = (xc40 == 39) ? 0 : xc40 + 1;
    };

    // prologue: stages 0..2
#pragma unroll
    for (int s = 0; s < NSTAGE - 1; ++s) {
        issue(sb + s * STAGE_STRIDE);
        CP_COMMIT();
    }

    for (int s = 0; s < NSTEP; ++s) {
        CP_WAIT(2);
        __syncthreads();
        if (s + NSTAGE - 1 < NSTEP)
            issue(sb + ((s + NSTAGE - 1) & (NSTAGE - 1)) * STAGE_STRIDE);
        CP_COMMIT();

        const uint32_t stgA = sb + (s & (NSTAGE - 1)) * STAGE_STRIDE;
        const uint32_t stgB = stgA + OFF_B;

#pragma unroll
        for (int kh = 0; kh < 2; ++kh) {
            const uint32_t ch = 2u * kh + hl;        // hi chunk (0..3)
            const uint32_t cl = ch + 4u;             // lo chunk (4..7)
            // ---- load all fragments up front ----
            uint32_t bh[8], bl[8], ah[4][4];
            ldsm4(bh[0], bh[1], bh[2], bh[3], stgB + bLaneOff +    0 + 16u * (ch ^ swz));
            ldsm4(bh[4], bh[5], bh[6], bh[7], stgB + bLaneOff + 2048 + 16u * (ch ^ swz));
            ldsm4(bl[0], bl[1], bl[2], bl[3], stgB + bLaneOff +    0 + 16u * (cl ^ swz));
            ldsm4(bl[4], bl[5], bl[6], bl[7], stgB + bLaneOff + 2048 + 16u * (cl ^ swz));
#pragma unroll
            for (int mi = 0; mi < 4; ++mi)
                ldsm4(ah[mi][0], ah[mi][1], ah[mi][2], ah[mi][3],
                      stgA + aLaneOff + mi * 2048 + 16u * (ch ^ swz));

            // Fragment pairing: ldsm4 reg order r0={nLO,kLO} r1={nHI,kLO}
            // r2={nLO,kHI} r3={nHI,kHI}; mma {b0,b1} = {kLO,kHI} of one n-group:
            //   nt -> b0 = (nt&1) + (nt>>1)*4, b1 = b0+2.
            // Term-major issue order: same-accumulator reuse distance >= 16 MMAs.
            // ---- term 1: Ah * Bh ----
#pragma unroll
            for (int mi = 0; mi < 4; ++mi)
#pragma unroll
                for (int nt = 0; nt < 4; ++nt) {
                    const int b0 = (nt & 1) + (nt >> 1) * 4;
                    mma16816(acc[mi][nt][0], acc[mi][nt][1], acc[mi][nt][2], acc[mi][nt][3],
                             ah[mi][0], ah[mi][1], ah[mi][2], ah[mi][3],
                             bh[b0], bh[b0 + 2]);
                }
            // ---- term 2: Ah * Bl (reuses ah) ----
#pragma unroll
            for (int mi = 0; mi < 4; ++mi)
#pragma unroll
                for (int nt = 0; nt < 4; ++nt) {
                    const int b0 = (nt & 1) + (nt >> 1) * 4;
                    mma16816(acc[mi][nt][0], acc[mi][nt][1], acc[mi][nt][2], acc[mi][nt][3],
                             ah[mi][0], ah[mi][1], ah[mi][2], ah[mi][3],
                             bl[b0], bl[b0 + 2]);
                }
            // ---- term 3: Al * Bh (al transient per mi) ----
#pragma unroll
            for (int mi = 0; mi < 4; ++mi) {
                uint32_t al[4];
                ldsm4(al[0], al[1], al[2], al[3],
                      stgA + aLaneOff + mi * 2048 + 16u * (cl ^ swz));
#pragma unroll
                for (int nt = 0; nt < 4; ++nt) {
                    const int b0 = (nt & 1) + (nt >> 1) * 4;
                    mma16816(acc[mi][nt][0], acc[mi][nt][1], acc[mi][nt][2], acc[mi][nt][3],
                             al[0], al[1], al[2], al[3],
                             bh[b0], bh[b0 + 2]);
                }
            }
        }
    }

    // ---- epilogue: stores + BN stats ----
    const int lg = l >> 2;          // acc row group within 16-row tile
    const int lc = l & 3;           // acc col group (2 cols each)
    const int orow = i0 + ((w & 7) >> 1);
    const int jb   = (w & 1) * 32;

#pragma unroll
    for (int mi = 0; mi < 4; ++mi) {
#pragma unroll
        for (int h = 0; h < 2; ++h) {
            const int m = mbase + mrow0 + mi * 16 + lg + h * 8;
            float* rowp = out + (((size_t)(b * 256 + m)) * 64 + orow) * 64 + jb + 2 * lc;
            float s = 0.f, sq = 0.f;
#pragma unroll
            for (int nt = 0; nt < 4; ++nt) {
                float c0 = acc[mi][nt][2 * h];
                float c1 = acc[mi][nt][2 * h + 1];
                reinterpret_cast<float2*>(rowp + nt * 8)[0] = make_float2(c0, c1);
                s  += c0 + c1;
                sq += c0 * c0 + c1 * c1;
            }
            s  += __shfl_xor_sync(0xffffffffu, s,  1);
            s  += __shfl_xor_sync(0xffffffffu, s,  2);
            sq += __shfl_xor_sync(0xffffffffu, sq, 1);
            sq += __shfl_xor_sync(0xffffffffu, sq, 2);
            if (lc == 0) {
                atomicAdd(&g_sum[m], s);
                atomicAdd(&g_sqsum[m], sq);
            }
        }
    }
}

// ---------------- BN normalize ----------------
__global__ void bn_kernel(float* __restrict__ out,
                          const float* __restrict__ gamma,
                          const float* __restrict__ beta)
{
    const long total4 = (long)Bn * COUTc * Hdim * Wdim / 4;
    long i4 = (long)blockIdx.x * blockDim.x + threadIdx.x;
    if (i4 >= total4) return;
    int c = (int)(i4 >> 10) & (COUTc - 1);
    const float invN = 1.0f / (float)(Bn * Hdim * Wdim);
    float mean  = g_sum[c] * invN;
    float var   = g_sqsum[c] * invN - mean * mean;
    float scale = gamma[c] * rsqrtf(var + 1e-5f);
    float shift = beta[c] - mean * scale;
    float4 v = reinterpret_cast<float4*>(out)[i4];
    v.x = v.x * scale + shift;
    v.y = v.y * scale + shift;
    v.z = v.z * scale + shift;
    v.w = v.w * scale + shift;
    reinterpret_cast<float4*>(out)[i4] = v;
}

// ---------------- launch ----------------
extern "C" void kernel_launch(void* const* d_in, const int* in_sizes, int n_in,
                              void* d_out, int out_size)
{
    const float* x     = (const float*)d_in[0];
    const float* w     = (const float*)d_in[1];
    const float* gamma = (const float*)d_in[2];
    const float* beta  = (const float*)d_in[3];
    float* out = (float*)d_out;

    cudaFuncSetAttribute(gemm_kernel, cudaFuncAttributeMaxDynamicSharedMemorySize,
                         SMEM_TOTAL);

    prep_w_kernel<<<70400, 256>>>(w);
    prep_x_kernel<<<65280, 256>>>(x);
    zero_stats_kernel<<<1, 256>>>();

    dim3 grid(2, 128);                     // 256 CTAs: 2 m-halves x (8 batch * 16 row-blocks)
    gemm_kernel<<<grid, 512, SMEM_TOTAL>>>(out);

    const long total4 = (long)Bn * COUTc * Hdim * Wdim / 4;
    bn_kernel<<<(unsigned)((total4 + 255) / 256), 256>>>(out, gamma, beta);
}

// round 6
// speedup vs baseline: 2.9357x; 1.0232x over previous
#include <cuda_runtime.h>
#include <cuda_bf16.h>
#include <stdint.h>

// ---------------- problem constants ----------------
#define Bn    8
#define CINc  256
#define COUTc 256
#define Hdim  64
#define Wdim  64
#define HP    120      // padded rows (h' = h + 25 in [0,118))
#define WP    68       // padded cols (w' = w + 2 in [0,68))
#define NTAP  275      // 55 t * 5 kw
#define NSTEP 2200     // 275 taps * 8 ci-chunks of 32

// ---------------- smem ----------------
#define OFF_B        16384          // A: [128][128B] = 16KB, B: [128][128B] = 16KB
#define STAGE_STRIDE 32768          // 32KB per stage
#define NSTAGE       3
#define SMEM_TOTAL   (STAGE_STRIDE * NSTAGE)   // 96KB -> 2 CTAs/SM

// ---------------- device scratch (static globals; no allocs) ----------------
__device__ __align__(256) __nv_bfloat16 g_xh[(size_t)Bn * HP * WP * CINc];
__device__ __align__(256) __nv_bfloat16 g_xl[(size_t)Bn * HP * WP * CINc];
__device__ __align__(256) __nv_bfloat16 g_wh[(size_t)NTAP * COUTc * CINc];
__device__ __align__(256) __nv_bfloat16 g_wl[(size_t)NTAP * COUTc * CINc];
__device__ float g_sum[COUTc];
__device__ float g_sqsum[COUTc];

// ---------------- PTX helpers (arch-generic: sm_80-era ops only) ----------------
__device__ __forceinline__ uint32_t smem_u32(const void* p) {
    uint32_t a;
    asm("{ .reg .u64 t; cvta.to.shared.u64 t, %1; cvt.u32.u64 %0, t; }"
        : "=r"(a) : "l"(p));
    return a;
}
__device__ __forceinline__ void cp16(uint32_t dst, const void* src) {
    asm volatile("cp.async.cg.shared.global [%0], [%1], 16;"
                 :: "r"(dst), "l"(src) : "memory");
}
#define CP_COMMIT() asm volatile("cp.async.commit_group;" ::: "memory")
#define CP_WAIT(n)  asm volatile("cp.async.wait_group %0;" :: "n"(n) : "memory")

__device__ __forceinline__ void ldsm4(uint32_t& r0, uint32_t& r1,
                                      uint32_t& r2, uint32_t& r3, uint32_t a) {
    asm volatile("ldmatrix.sync.aligned.m8n8.x4.shared.b16 {%0,%1,%2,%3}, [%4];"
                 : "=r"(r0), "=r"(r1), "=r"(r2), "=r"(r3) : "r"(a));
}
__device__ __forceinline__ void mma16816(float& d0, float& d1, float& d2, float& d3,
                                         uint32_t a0, uint32_t a1, uint32_t a2, uint32_t a3,
                                         uint32_t b0, uint32_t b1) {
    asm volatile("mma.sync.aligned.m16n8k16.row.col.f32.bf16.bf16.f32 "
                 "{%0,%1,%2,%3},{%4,%5,%6,%7},{%8,%9},{%0,%1,%2,%3};"
                 : "+f"(d0), "+f"(d1), "+f"(d2), "+f"(d3)
                 : "r"(a0), "r"(a1), "r"(a2), "r"(a3), "r"(b0), "r"(b1));
}

// ---------------- prep kernels ----------------
__global__ void prep_w_kernel(const float* __restrict__ w) {
    int idx = blockIdx.x * 256 + threadIdx.x;   // 275*256*256
    int ci  = idx & 255;
    int co  = (idx >> 8) & 255;
    int tap = idx >> 16;
    int t = tap / 5, kw = tap - 5 * t;
    int ik = t / 5,  kh = t - 5 * ik;
    float f = w[(((size_t)(co * 11 + ik) * 256 + ci) * 25) + kh * 5 + kw];
    __nv_bfloat16 hi = __float2bfloat16(f);
    __nv_bfloat16 lo = __float2bfloat16(f - __bfloat162float(hi));
    g_wh[idx] = hi;
    g_wl[idx] = lo;
}

__global__ void prep_x_kernel(const float* __restrict__ x) {
    int idx = blockIdx.x * 256 + threadIdx.x;   // 8*120*68*256
    int ci   = idx & 255;
    int rest = idx >> 8;
    int wp = rest % WP;
    int r2 = rest / WP;
    int hp = r2 % HP;
    int b  = r2 / HP;
    int h = hp - 25, wq = wp - 2;
    float v = 0.f;
    if ((unsigned)h < 64u && (unsigned)wq < 64u)
        v = x[(((size_t)(b * 256 + ci) * 64) + h) * 64 + wq];
    __nv_bfloat16 hi = __float2bfloat16(v);
    __nv_bfloat16 lo = __float2bfloat16(v - __bfloat162float(hi));
    g_xh[idx] = hi;
    g_xl[idx] = lo;
}

__global__ void zero_stats_kernel() {
    int t = threadIdx.x;
    if (t < COUTc) { g_sum[t] = 0.f; g_sqsum[t] = 0.f; }
}

// ---------------- main GEMM kernel (256 thr, 2 CTAs/SM) ----------------
__global__ __launch_bounds__(256, 2)
void gemm_kernel(float* __restrict__ out)
{
    extern __shared__ __align__(1024) char smem[];
    const uint32_t sb = smem_u32(smem);

    const int tid  = threadIdx.x;
    const int w    = tid >> 5;               // 8 warps: 2m x 4n
    const int l    = tid & 31;
    const int mbase = blockIdx.x * 128;
    const int nblk  = blockIdx.y;            // 256 n-tiles
    const int b     = nblk >> 5;
    const int i0    = (nblk & 31) * 2;       // 2 output rows per CTA

    // ---- copy geometry (per thread): 4 A-rows + 4 B-rows, 16B each ----
    const int cA  = tid & 7;                 // 16B chunk within 128B row
    const int rA0 = tid >> 3;                // 0..31
    const uint32_t swc = 16u * (uint32_t)(cA ^ (rA0 & 7));
    const __nv_bfloat16* srcW = (cA < 4) ? g_wh : g_wl;
    const __nv_bfloat16* srcX = (cA < 4) ? g_xh : g_xl;
    const uint32_t adst = (uint32_t)rA0 * 128 + swc;   // rows rA0+32k at +4096*k

    // incremental source pointers (bf16 element units)
    const __nv_bfloat16* aptr = srcW + (size_t)(mbase + rA0) * 256 + (size_t)(cA & 3) * 8;
    const __nv_bfloat16* xptr = srcX + (size_t)b * (HP * WP * 256)
                              + ((size_t)i0 * WP + rA0) * 256 + (size_t)(cA & 3) * 8;
    int ac8 = 0;     // A: every 8th issue jumps a tap
    int xc40 = 0;    // X: every 40th issue jumps a t-row

    // ---- mma geometry (per warp/lane) ----
    const int mrow0 = (w >> 2) * 64;
    const int nrow0 = (w & 3) * 32;
    const uint32_t swz = (uint32_t)(l & 7);
    const uint32_t hl  = (uint32_t)(l >> 4);
    const uint32_t aLaneOff = (uint32_t)(mrow0 + (l & 15)) * 128;
    const uint32_t bLaneOff = (uint32_t)(nrow0 + (l & 7) + ((l >> 3) & 1) * 8) * 128;

    float acc[4][4][4];
#pragma unroll
    for (int mi = 0; mi < 4; ++mi)
#pragma unroll
        for (int nt = 0; nt < 4; ++nt)
#pragma unroll
            for (int r = 0; r < 4; ++r) acc[mi][nt][r] = 0.f;

    // ---- issue one 32KB stage ----
    auto issue = [&](uint32_t stg) {
#pragma unroll
        for (int k = 0; k < 4; ++k)
            cp16(stg + adst + k * 4096, aptr + k * 8192);
        // B rows rA0+32k: k-offsets {0, 8192, WP*256, WP*256+8192}
        cp16(stg + OFF_B + adst,         xptr);
        cp16(stg + OFF_B + adst + 4096,  xptr + 8192);
        cp16(stg + OFF_B + adst + 8192,  xptr + 17408);
        cp16(stg + OFF_B + adst + 12288, xptr + 25600);
        aptr += (ac8 == 7) ? 65312 : 32;
        ac8 = (ac8 + 1) & 7;
        xptr += (xc40 == 39) ? 16160 : 32;
        xc40 = (xc40 == 39) ? 0 : xc40 + 1;
    };

    // prologue: stages 0,1
    issue(sb);                    CP_COMMIT();
    issue(sb + STAGE_STRIDE);     CP_COMMIT();

    int prod = 2, cons = 0;
    for (int s = 0; s < NSTEP; ++s) {
        CP_WAIT(1);
        __syncthreads();
        if (s + 2 < NSTEP)
            issue(sb + prod * STAGE_STRIDE);
        CP_COMMIT();

        const uint32_t stgA = sb + cons * STAGE_STRIDE;
        const uint32_t stgB = stgA + OFF_B;
        prod = (prod == 2) ? 0 : prod + 1;
        cons = (cons == 2) ? 0 : cons + 1;

#pragma unroll
        for (int kh = 0; kh < 2; ++kh) {
            const uint32_t ch = 2u * kh + hl;        // hi chunk (0..3)
            const uint32_t cl = ch + 4u;             // lo chunk (4..7)
            uint32_t bh[8], bl[8], ah[4][4];
            ldsm4(bh[0], bh[1], bh[2], bh[3], stgB + bLaneOff +    0 + 16u * (ch ^ swz));
            ldsm4(bh[4], bh[5], bh[6], bh[7], stgB + bLaneOff + 2048 + 16u * (ch ^ swz));
            ldsm4(bl[0], bl[1], bl[2], bl[3], stgB + bLaneOff +    0 + 16u * (cl ^ swz));
            ldsm4(bl[4], bl[5], bl[6], bl[7], stgB + bLaneOff + 2048 + 16u * (cl ^ swz));
#pragma unroll
            for (int mi = 0; mi < 4; ++mi)
                ldsm4(ah[mi][0], ah[mi][1], ah[mi][2], ah[mi][3],
                      stgA + aLaneOff + mi * 2048 + 16u * (ch ^ swz));

            // ldsm4 reg order r0={nLO,kLO} r1={nHI,kLO} r2={nLO,kHI} r3={nHI,kHI}
            // mma {b0,b1} = {kLO,kHI} of one n-group: b0 = (nt&1)+(nt>>1)*4, b1 = b0+2.
#pragma unroll
            for (int mi = 0; mi < 4; ++mi)
#pragma unroll
                for (int nt = 0; nt < 4; ++nt) {
                    const int b0 = (nt & 1) + (nt >> 1) * 4;
                    mma16816(acc[mi][nt][0], acc[mi][nt][1], acc[mi][nt][2], acc[mi][nt][3],
                             ah[mi][0], ah[mi][1], ah[mi][2], ah[mi][3],
                             bh[b0], bh[b0 + 2]);
                }
#pragma unroll
            for (int mi = 0; mi < 4; ++mi)
#pragma unroll
                for (int nt = 0; nt < 4; ++nt) {
                    const int b0 = (nt & 1) + (nt >> 1) * 4;
                    mma16816(acc[mi][nt][0], acc[mi][nt][1], acc[mi][nt][2], acc[mi][nt][3],
                             ah[mi][0], ah[mi][1], ah[mi][2], ah[mi][3],
                             bl[b0], bl[b0 + 2]);
                }
#pragma unroll
            for (int mi = 0; mi < 4; ++mi) {
                uint32_t al[4];
                ldsm4(al[0], al[1], al[2], al[3],
                      stgA + aLaneOff + mi * 2048 + 16u * (cl ^ swz));
#pragma unroll
                for (int nt = 0; nt < 4; ++nt) {
                    const int b0 = (nt & 1) + (nt >> 1) * 4;
                    mma16816(acc[mi][nt][0], acc[mi][nt][1], acc[mi][nt][2], acc[mi][nt][3],
                             al[0], al[1], al[2], al[3],
                             bh[b0], bh[b0 + 2]);
                }
            }
        }
    }

    // ---- epilogue: stores + BN stats ----
    const int lg = l >> 2;
    const int lc = l & 3;
    const int orow = i0 + ((w & 3) >> 1);
    const int jb   = (w & 1) * 32;

#pragma unroll
    for (int mi = 0; mi < 4; ++mi) {
#pragma unroll
        for (int h = 0; h < 2; ++h) {
            const int m = mbase + mrow0 + mi * 16 + lg + h * 8;
            float* rowp = out + (((size_t)(b * 256 + m)) * 64 + orow) * 64 + jb + 2 * lc;
            float s = 0.f, sq = 0.f;
#pragma unroll
            for (int nt = 0; nt < 4; ++nt) {
                float c0 = acc[mi][nt][2 * h];
                float c1 = acc[mi][nt][2 * h + 1];
                reinterpret_cast<float2*>(rowp + nt * 8)[0] = make_float2(c0, c1);
                s  += c0 + c1;
                sq += c0 * c0 + c1 * c1;
            }
            s  += __shfl_xor_sync(0xffffffffu, s,  1);
            s  += __shfl_xor_sync(0xffffffffu, s,  2);
            sq += __shfl_xor_sync(0xffffffffu, sq, 1);
            sq += __shfl_xor_sync(0xffffffffu, sq, 2);
            if (lc == 0) {
                atomicAdd(&g_sum[m], s);
                atomicAdd(&g_sqsum[m], sq);
            }
        }
    }
}

// ---------------- BN normalize ----------------
__global__ void bn_kernel(float* __restrict__ out,
                          const float* __restrict__ gamma,
                          const float* __restrict__ beta)
{
    const long total4 = (long)Bn * COUTc * Hdim * Wdim / 4;
    long i4 = (long)blockIdx.x * blockDim.x + threadIdx.x;
    if (i4 >= total4) return;
    int c = (int)(i4 >> 10) & (COUTc - 1);
    const float invN = 1.0f / (float)(Bn * Hdim * Wdim);
    float mean  = g_sum[c] * invN;
    float var   = g_sqsum[c] * invN - mean * mean;
    float scale = gamma[c] * rsqrtf(var + 1e-5f);
    float shift = beta[c] - mean * scale;
    float4 v = reinterpret_cast<float4*>(out)[i4];
    v.x = v.x * scale + shift;
    v.y = v.y * scale + shift;
    v.z = v.z * scale + shift;
    v.w = v.w * scale + shift;
    reinterpret_cast<float4*>(out)[i4] = v;
}

// ---------------- launch ----------------
extern "C" void kernel_launch(void* const* d_in, const int* in_sizes, int n_in,
                              void* d_out, int out_size)
{
    const float* x     = (const float*)d_in[0];
    const float* w     = (const float*)d_in[1];
    const float* gamma = (const float*)d_in[2];
    const float* beta  = (const float*)d_in[3];
    float* out = (float*)d_out;

    cudaFuncSetAttribute(gemm_kernel, cudaFuncAttributeMaxDynamicSharedMemorySize,
                         SMEM_TOTAL);

    prep_w_kernel<<<70400, 256>>>(w);
    prep_x_kernel<<<65280, 256>>>(x);
    zero_stats_kernel<<<1, 256>>>();

    dim3 grid(2, 256);                     // 512 CTAs, 2 per SM
    gemm_kernel<<<grid, 256, SMEM_TOTAL>>>(out);

    const long total4 = (long)Bn * COUTc * Hdim * Wdim / 4;
    bn_kernel<<<(unsigned)((total4 + 255) / 256), 256>>>(out, gamma, beta);
}

// round 8
// speedup vs baseline: 2.9371x; 1.0005x over previous
#include <cuda_runtime.h>
#include <cuda_bf16.h>
#include <stdint.h>

// ---------------- problem constants ----------------
#define Bn    8
#define CINc  256
#define COUTc 256
#define Hdim  64
#define Wdim  64
#define HP    120
#define WP    68
#define NTAP  275
#define NSTEP 2200     // 275 taps * 8 ci-chunks of 32

// ---------------- smem ----------------
#define OFF_B        16384
#define STAGE_STRIDE 32768
#define SMEM_TOTAL   (STAGE_STRIDE * 3)    // 96KB -> 2 CTAs/SM

// ---------------- device scratch ----------------
__device__ __align__(256) __nv_bfloat16 g_xh[(size_t)Bn * HP * WP * CINc];
__device__ __align__(256) __nv_bfloat16 g_xl[(size_t)Bn * HP * WP * CINc];
__device__ __align__(256) __nv_bfloat16 g_wh[(size_t)NTAP * COUTc * CINc];
__device__ __align__(256) __nv_bfloat16 g_wl[(size_t)NTAP * COUTc * CINc];
__device__ float g_sum[COUTc];
__device__ float g_sqsum[COUTc];

// ---------------- PTX helpers ----------------
__device__ __forceinline__ uint32_t smem_u32(const void* p) {
    uint32_t a;
    asm("{ .reg .u64 t; cvta.to.shared.u64 t, %1; cvt.u32.u64 %0, t; }"
        : "=r"(a) : "l"(p));
    return a;
}
__device__ __forceinline__ void cp16(uint32_t dst, const void* src) {
    asm volatile("cp.async.cg.shared.global [%0], [%1], 16;"
                 :: "r"(dst), "l"(src) : "memory");
}
#define CP_COMMIT() asm volatile("cp.async.commit_group;" ::: "memory")
#define CP_WAIT(n)  asm volatile("cp.async.wait_group %0;" :: "n"(n) : "memory")

__device__ __forceinline__ void ldsm4(uint32_t& r0, uint32_t& r1,
                                      uint32_t& r2, uint32_t& r3, uint32_t a) {
    asm volatile("ldmatrix.sync.aligned.m8n8.x4.shared.b16 {%0,%1,%2,%3}, [%4];"
                 : "=r"(r0), "=r"(r1), "=r"(r2), "=r"(r3) : "r"(a));
}
__device__ __forceinline__ void mma16816(float& d0, float& d1, float& d2, float& d3,
                                         uint32_t a0, uint32_t a1, uint32_t a2, uint32_t a3,
                                         uint32_t b0, uint32_t b1) {
    asm volatile("mma.sync.aligned.m16n8k16.row.col.f32.bf16.bf16.f32 "
                 "{%0,%1,%2,%3},{%4,%5,%6,%7},{%8,%9},{%0,%1,%2,%3};"
                 : "+f"(d0), "+f"(d1), "+f"(d2), "+f"(d3)
                 : "r"(a0), "r"(a1), "r"(a2), "r"(a3), "r"(b0), "r"(b1));
}

// ---------------- prep kernels ----------------
__global__ void prep_w_kernel(const float* __restrict__ w) {
    int idx = blockIdx.x * 256 + threadIdx.x;
    int ci  = idx & 255;
    int co  = (idx >> 8) & 255;
    int tap = idx >> 16;
    int t = tap / 5, kw = tap - 5 * t;
    int ik = t / 5,  kh = t - 5 * ik;
    float f = w[(((size_t)(co * 11 + ik) * 256 + ci) * 25) + kh * 5 + kw];
    __nv_bfloat16 hi = __float2bfloat16(f);
    __nv_bfloat16 lo = __float2bfloat16(f - __bfloat162float(hi));
    g_wh[idx] = hi;
    g_wl[idx] = lo;
}

__global__ void prep_x_kernel(const float* __restrict__ x) {
    int idx = blockIdx.x * 256 + threadIdx.x;
    int ci   = idx & 255;
    int rest = idx >> 8;
    int wp = rest % WP;
    int r2 = rest / WP;
    int hp = r2 % HP;
    int b  = r2 / HP;
    int h = hp - 25, wq = wp - 2;
    float v = 0.f;
    if ((unsigned)h < 64u && (unsigned)wq < 64u)
        v = x[(((size_t)(b * 256 + ci) * 64) + h) * 64 + wq];
    __nv_bfloat16 hi = __float2bfloat16(v);
    __nv_bfloat16 lo = __float2bfloat16(v - __bfloat162float(hi));
    g_xh[idx] = hi;
    g_xl[idx] = lo;
}

__global__ void zero_stats_kernel() {
    int t = threadIdx.x;
    if (t < COUTc) { g_sum[t] = 0.f; g_sqsum[t] = 0.f; }
}

// ---------------- main GEMM kernel (256 thr, 2 CTAs/SM) ----------------
__global__ __launch_bounds__(256, 2)
void gemm_kernel(float* __restrict__ out)
{
    extern __shared__ __align__(1024) char smem[];
    const uint32_t sb = smem_u32(smem);

    const int tid  = threadIdx.x;
    const int w    = tid >> 5;
    const int l    = tid & 31;
    const int mbase = blockIdx.x * 128;
    const int nblk  = blockIdx.y;
    const int b     = nblk >> 5;
    const int i0    = (nblk & 31) * 2;

    // ---- copy geometry ----
    const int cA  = tid & 7;
    const int rA0 = tid >> 3;
    const uint32_t swc = 16u * (uint32_t)(cA ^ (rA0 & 7));
    const __nv_bfloat16* srcW = (cA < 4) ? g_wh : g_wl;
    const __nv_bfloat16* srcX = (cA < 4) ? g_xh : g_xl;
    const uint32_t adst = sb + (uint32_t)rA0 * 128 + swc;

    const __nv_bfloat16* aptr = srcW + (size_t)(mbase + rA0) * 256 + (size_t)(cA & 3) * 8;
    const __nv_bfloat16* xptr = srcX + (size_t)b * (HP * WP * 256)
                              + ((size_t)i0 * WP + rA0) * 256 + (size_t)(cA & 3) * 8;
    int ac8 = 0;
    int xc40 = 0;

    // ---- mma geometry ----
    const int mrow0 = (w >> 2) * 64;
    const int nrow0 = (w & 3) * 32;
    const uint32_t swz = (uint32_t)(l & 7);
    const uint32_t hl  = (uint32_t)(l >> 4);
    const uint32_t aLaneOff = (uint32_t)(mrow0 + (l & 15)) * 128;
    const uint32_t bLaneOff = (uint32_t)(nrow0 + (l & 7) + ((l >> 3) & 1) * 8) * 128;

    // Precomputed hi-chunk ldsm bases per kh (sb folded in ONCE).
    // Lo-chunk address = hi ^ 64: 16*((ch+4)^swz) = 16*(ch^swz) ^ 64 for ch<4,
    // and all other address components are multiples of 128.
    uint32_t aB[2], bB[2];
#pragma unroll
    for (int kh = 0; kh < 2; ++kh) {
        const uint32_t ch = 2u * kh + hl;
        aB[kh] = sb + aLaneOff + 16u * (ch ^ swz);
        bB[kh] = sb + OFF_B + bLaneOff + 16u * (ch ^ swz);
    }

    float acc[4][4][4];
#pragma unroll
    for (int mi = 0; mi < 4; ++mi)
#pragma unroll
        for (int nt = 0; nt < 4; ++nt)
#pragma unroll
            for (int r = 0; r < 4; ++r) acc[mi][nt][r] = 0.f;

    // ---- issue one 32KB stage at literal stage offset ----
    auto issue = [&](const uint32_t so) {
#pragma unroll
        for (int k = 0; k < 4; ++k)
            cp16(so + adst + k * 4096, aptr + k * 8192);
        cp16(so + OFF_B + adst,         xptr);
        cp16(so + OFF_B + adst + 4096,  xptr + 8192);
        cp16(so + OFF_B + adst + 8192,  xptr + 17408);
        cp16(so + OFF_B + adst + 12288, xptr + 25600);
        aptr += (ac8 == 7) ? 65312 : 32;
        ac8 = (ac8 + 1) & 7;
        xptr += (xc40 == 39) ? 16160 : 32;
        xc40 = (xc40 == 39) ? 0 : xc40 + 1;
    };

    // ---- compute one step from literal stage offset (NOT including sb) ----
    auto compute = [&](const uint32_t so) {
#pragma unroll
        for (int kh = 0; kh < 2; ++kh) {
            uint32_t bh[8], bl[8], ah[4][4];
            ldsm4(bh[0], bh[1], bh[2], bh[3], bB[kh] + so);
            ldsm4(bh[4], bh[5], bh[6], bh[7], bB[kh] + so + 2048);
            ldsm4(bl[0], bl[1], bl[2], bl[3], (bB[kh] + so) ^ 64u);
            ldsm4(bl[4], bl[5], bl[6], bl[7], (bB[kh] + so + 2048) ^ 64u);
#pragma unroll
            for (int mi = 0; mi < 4; ++mi)
                ldsm4(ah[mi][0], ah[mi][1], ah[mi][2], ah[mi][3],
                      aB[kh] + so + mi * 2048);

            // ldsm4 reg order r0={nLO,kLO} r1={nHI,kLO} r2={nLO,kHI} r3={nHI,kHI}
            // mma {b0,b1} = {kLO,kHI} of one n-group: b0=(nt&1)+(nt>>1)*4, b1=b0+2.
#pragma unroll
            for (int mi = 0; mi < 4; ++mi)
#pragma unroll
                for (int nt = 0; nt < 4; ++nt) {
                    const int b0 = (nt & 1) + (nt >> 1) * 4;
                    mma16816(acc[mi][nt][0], acc[mi][nt][1], acc[mi][nt][2], acc[mi][nt][3],
                             ah[mi][0], ah[mi][1], ah[mi][2], ah[mi][3],
                             bh[b0], bh[b0 + 2]);
                }
#pragma unroll
            for (int mi = 0; mi < 4; ++mi)
#pragma unroll
                for (int nt = 0; nt < 4; ++nt) {
                    const int b0 = (nt & 1) + (nt >> 1) * 4;
                    mma16816(acc[mi][nt][0], acc[mi][nt][1], acc[mi][nt][2], acc[mi][nt][3],
                             ah[mi][0], ah[mi][1], ah[mi][2], ah[mi][3],
                             bl[b0], bl[b0 + 2]);
                }
#pragma unroll
            for (int mi = 0; mi < 4; ++mi) {
                uint32_t al[4];
                ldsm4(al[0], al[1], al[2], al[3],
                      (aB[kh] + so + mi * 2048) ^ 64u);
#pragma unroll
                for (int nt = 0; nt < 4; ++nt) {
                    const int b0 = (nt & 1) + (nt >> 1) * 4;
                    mma16816(acc[mi][nt][0], acc[mi][nt][1], acc[mi][nt][2], acc[mi][nt][3],
                             al[0], al[1], al[2], al[3],
                             bh[b0], bh[b0 + 2]);
                }
            }
        }
    };

    // prologue: steps 0,1 -> stages 0,1
    issue(0);              CP_COMMIT();
    issue(STAGE_STRIDE);   CP_COMMIT();

    // main: 733 iterations x 3 steps, all stage offsets compile-time.
    // Step s = 3*i+u: consume stage u, produce stage (u+2)%3 for step s+2.
    for (int i = 0; i < 733; ++i) {
#pragma unroll
        for (int u = 0; u < 3; ++u) {
            CP_WAIT(1);
            __syncthreads();
            const int s = 3 * i + u;
            if (s + 2 < NSTEP)
                issue((uint32_t)(((u + 2) % 3) * STAGE_STRIDE));
            CP_COMMIT();
            compute((uint32_t)(u * STAGE_STRIDE));
        }
    }
    // tail: step 2199 -> stage 0
    CP_WAIT(0);
    __syncthreads();
    compute(0);

    // ---- epilogue: stores + BN stats ----
    const int lg = l >> 2;
    const int lc = l & 3;
    const int orow = i0 + ((w & 3) >> 1);
    const int jb   = (w & 1) * 32;

#pragma unroll
    for (int mi = 0; mi < 4; ++mi) {
#pragma unroll
        for (int h = 0; h < 2; ++h) {
            const int m = mbase + mrow0 + mi * 16 + lg + h * 8;
            float* rowp = out + (((size_t)(b * 256 + m)) * 64 + orow) * 64 + jb + 2 * lc;
            float s = 0.f, sq = 0.f;
#pragma unroll
            for (int nt = 0; nt < 4; ++nt) {
                float c0 = acc[mi][nt][2 * h];
                float c1 = acc[mi][nt][2 * h + 1];
                reinterpret_cast<float2*>(rowp + nt * 8)[0] = make_float2(c0, c1);
                s  += c0 + c1;
                sq += c0 * c0 + c1 * c1;
            }
            s  += __shfl_xor_sync(0xffffffffu, s,  1);
            s  += __shfl_xor_sync(0xffffffffu, s,  2);
            sq += __shfl_xor_sync(0xffffffffu, sq, 1);
            sq += __shfl_xor_sync(0xffffffffu, sq, 2);
            if (lc == 0) {
                atomicAdd(&g_sum[m], s);
                atomicAdd(&g_sqsum[m], sq);
            }
        }
    }
}

// ---------------- BN normalize ----------------
__global__ void bn_kernel(float* __restrict__ out,
                          const float* __restrict__ gamma,
                          const float* __restrict__ beta)
{
    const long total4 = (long)Bn * COUTc * Hdim * Wdim / 4;
    long i4 = (long)blockIdx.x * blockDim.x + threadIdx.x;
    if (i4 >= total4) return;
    int c = (int)(i4 >> 10) & (COUTc - 1);
    const float invN = 1.0f / (float)(Bn * Hdim * Wdim);
    float mean  = g_sum[c] * invN;
    float var   = g_sqsum[c] * invN - mean * mean;
    float scale = gamma[c] * rsqrtf(var + 1e-5f);
    float shift = beta[c] - mean * scale;
    float4 v = reinterpret_cast<float4*>(out)[i4];
    v.x = v.x * scale + shift;
    v.y = v.y * scale + shift;
    v.z = v.z * scale + shift;
    v.w = v.w * scale + shift;
    reinterpret_cast<float4*>(out)[i4] = v;
}

// ---------------- launch ----------------
extern "C" void kernel_launch(void* const* d_in, const int* in_sizes, int n_in,
                              void* d_out, int out_size)
{
    const float* x     = (const float*)d_in[0];
    const float* w     = (const float*)d_in[1];
    const float* gamma = (const float*)d_in[2];
    const float* beta  = (const float*)d_in[3];
    float* out = (float*)d_out;

    cudaFuncSetAttribute(gemm_kernel, cudaFuncAttributeMaxDynamicSharedMemorySize,
                         SMEM_TOTAL);

    prep_w_kernel<<<70400, 256>>>(w);
    prep_x_kernel<<<65280, 256>>>(x);
    zero_stats_kernel<<<1, 256>>>();

    dim3 grid(2, 256);
    gemm_kernel<<<grid, 256, SMEM_TOTAL>>>(out);

    const long total4 = (long)Bn * COUTc * Hdim * Wdim / 4;
    bn_kernel<<<(unsigned)((total4 + 255) / 256), 256>>>(out, gamma, beta);
}

// round 9
// speedup vs baseline: 4.2759x; 1.4558x over previous
#include <cuda_runtime.h>
#include <cuda_fp16.h>
#include <stdint.h>

// ---------------- problem constants ----------------
#define Bn    8
#define CINc  256
#define COUTc 256
#define Hdim  64
#define Wdim  64
#define HP    120
#define WP    68
#define NTAP  275
#define NSTEP 2200     // 275 taps * 8 ci-chunks of 32

// ---------------- smem ----------------
#define OFF_B        16384
#define STAGE_STRIDE 32768
#define SMEM_TOTAL   (STAGE_STRIDE * 3)    // 96KB -> 2 CTAs/SM

// ---------------- device scratch ----------------
__device__ __align__(256) __half g_xq[(size_t)Bn * HP * WP * CINc];   // x, 1 fp16 limb
__device__ __align__(256) __half g_wh[(size_t)NTAP * COUTc * CINc];   // w hi limb
__device__ __align__(256) __half g_wl[(size_t)NTAP * COUTc * CINc];   // w lo limb
__device__ float g_sum[COUTc];
__device__ float g_sqsum[COUTc];

// ---------------- PTX helpers ----------------
__device__ __forceinline__ uint32_t smem_u32(const void* p) {
    uint32_t a;
    asm("{ .reg .u64 t; cvta.to.shared.u64 t, %1; cvt.u32.u64 %0, t; }"
        : "=r"(a) : "l"(p));
    return a;
}
__device__ __forceinline__ void cp16(uint32_t dst, const void* src) {
    asm volatile("cp.async.cg.shared.global [%0], [%1], 16;"
                 :: "r"(dst), "l"(src) : "memory");
}
#define CP_COMMIT() asm volatile("cp.async.commit_group;" ::: "memory")
#define CP_WAIT(n)  asm volatile("cp.async.wait_group %0;" :: "n"(n) : "memory")

__device__ __forceinline__ void ldsm4(uint32_t& r0, uint32_t& r1,
                                      uint32_t& r2, uint32_t& r3, uint32_t a) {
    asm volatile("ldmatrix.sync.aligned.m8n8.x4.shared.b16 {%0,%1,%2,%3}, [%4];"
                 : "=r"(r0), "=r"(r1), "=r"(r2), "=r"(r3) : "r"(a));
}
__device__ __forceinline__ void mma16816(float& d0, float& d1, float& d2, float& d3,
                                         uint32_t a0, uint32_t a1, uint32_t a2, uint32_t a3,
                                         uint32_t b0, uint32_t b1) {
    asm volatile("mma.sync.aligned.m16n8k16.row.col.f32.f16.f16.f32 "
                 "{%0,%1,%2,%3},{%4,%5,%6,%7},{%8,%9},{%0,%1,%2,%3};"
                 : "+f"(d0), "+f"(d1), "+f"(d2), "+f"(d3)
                 : "r"(a0), "r"(a1), "r"(a2), "r"(a3), "r"(b0), "r"(b1));
}

// ---------------- prep kernels ----------------
__global__ void prep_w_kernel(const float* __restrict__ w) {
    int idx = blockIdx.x * 256 + threadIdx.x;
    int ci  = idx & 255;
    int co  = (idx >> 8) & 255;
    int tap = idx >> 16;
    int t = tap / 5, kw = tap - 5 * t;
    int ik = t / 5,  kh = t - 5 * ik;
    float f = w[(((size_t)(co * 11 + ik) * 256 + ci) * 25) + kh * 5 + kw];
    __half hi = __float2half(f);
    __half lo = __float2half(f - __half2float(hi));
    g_wh[idx] = hi;
    g_wl[idx] = lo;
}

__global__ void prep_x_kernel(const float* __restrict__ x) {
    int idx = blockIdx.x * 256 + threadIdx.x;
    int ci   = idx & 255;
    int rest = idx >> 8;
    int wp = rest % WP;
    int r2 = rest / WP;
    int hp = r2 % HP;
    int b  = r2 / HP;
    int h = hp - 25, wq = wp - 2;
    float v = 0.f;
    if ((unsigned)h < 64u && (unsigned)wq < 64u)
        v = x[(((size_t)(b * 256 + ci) * 64) + h) * 64 + wq];
    g_xq[idx] = __float2half(v);
}

__global__ void zero_stats_kernel() {
    int t = threadIdx.x;
    if (t < COUTc) { g_sum[t] = 0.f; g_sqsum[t] = 0.f; }
}

// ---------------- main GEMM kernel (256 thr, 2 CTAs/SM) ----------------
__global__ __launch_bounds__(256, 2)
void gemm_kernel(float* __restrict__ out)
{
    extern __shared__ __align__(1024) char smem[];
    const uint32_t sb = smem_u32(smem);

    const int tid  = threadIdx.x;
    const int w    = tid >> 5;
    const int l    = tid & 31;
    const int mbase = blockIdx.x * 128;
    const int nblk  = blockIdx.y;
    const int b     = nblk >> 5;
    const int i0    = (nblk & 31) * 2;

    // ---- A copy geometry (2 limbs interleaved per 128B row) ----
    const int cA  = tid & 7;
    const int rA0 = tid >> 3;
    const uint32_t swc = 16u * (uint32_t)(cA ^ (rA0 & 7));
    const __half* srcW = (cA < 4) ? g_wh : g_wl;
    const uint32_t adst = sb + (uint32_t)rA0 * 128 + swc;
    const __half* aptr = srcW + (size_t)(mbase + rA0) * 256 + (size_t)(cA & 3) * 8;

    // ---- B copy geometry (single limb: 64B of data per 128B row) ----
    const int cB  = tid & 3;                 // chunk 0..3
    const int rB0 = tid >> 2;                // rows rB0, rB0+64
    const uint32_t bdst0 = sb + OFF_B + (uint32_t)rB0 * 128
                         + 16u * (uint32_t)(cB ^ (rB0 & 7));
    const __half* xptr = g_xq + (size_t)b * (HP * WP * 256)
                       + ((size_t)i0 * WP + rB0) * 256 + (size_t)cB * 8;
    int ac8 = 0;
    int xc40 = 0;

    // ---- mma geometry ----
    const int mrow0 = (w >> 2) * 64;
    const int nrow0 = (w & 3) * 32;
    const uint32_t swz = (uint32_t)(l & 7);
    const uint32_t hl  = (uint32_t)(l >> 4);
    const uint32_t aLaneOff = (uint32_t)(mrow0 + (l & 15)) * 128;
    const uint32_t bLaneOff = (uint32_t)(nrow0 + (l & 7) + ((l >> 3) & 1) * 8) * 128;

    // Precomputed hi-chunk ldsm bases per kh; A lo-limb address = hi ^ 64.
    uint32_t aB[2], bB[2];
#pragma unroll
    for (int kh = 0; kh < 2; ++kh) {
        const uint32_t ch = 2u * kh + hl;
        aB[kh] = sb + aLaneOff + 16u * (ch ^ swz);
        bB[kh] = sb + OFF_B + bLaneOff + 16u * (ch ^ swz);
    }

    float acc[4][4][4];
#pragma unroll
    for (int mi = 0; mi < 4; ++mi)
#pragma unroll
        for (int nt = 0; nt < 4; ++nt)
#pragma unroll
            for (int r = 0; r < 4; ++r) acc[mi][nt][r] = 0.f;

    // ---- issue one stage: A 16KB (2 limbs) + B 8KB (1 limb) ----
    auto issue = [&](const uint32_t so) {
#pragma unroll
        for (int k = 0; k < 4; ++k)
            cp16(so + adst + k * 4096, aptr + k * 8192);
        cp16(so + bdst0,        xptr);
        cp16(so + bdst0 + 8192, xptr + 17408);    // row +64 -> orow+1 (WP*256)
        aptr += (ac8 == 7) ? 65312 : 32;
        ac8 = (ac8 + 1) & 7;
        xptr += (xc40 == 39) ? 16160 : 32;
        xc40 = (xc40 == 39) ? 0 : xc40 + 1;
    };

    // ---- compute one step (stage offset literal, excludes sb) ----
    auto compute = [&](const uint32_t so) {
#pragma unroll
        for (int kh = 0; kh < 2; ++kh) {
            uint32_t bh[8], ah[4][4];
            ldsm4(bh[0], bh[1], bh[2], bh[3], bB[kh] + so);
            ldsm4(bh[4], bh[5], bh[6], bh[7], bB[kh] + so + 2048);
#pragma unroll
            for (int mi = 0; mi < 4; ++mi)
                ldsm4(ah[mi][0], ah[mi][1], ah[mi][2], ah[mi][3],
                      aB[kh] + so + mi * 2048);

            // ldsm4 reg order r0={nLO,kLO} r1={nHI,kLO} r2={nLO,kHI} r3={nHI,kHI}
            // mma {b0,b1} = {kLO,kHI} of one n-group: b0=(nt&1)+(nt>>1)*4, b1=b0+2.
            // term 1: Wh * X
#pragma unroll
            for (int mi = 0; mi < 4; ++mi)
#pragma unroll
                for (int nt = 0; nt < 4; ++nt) {
                    const int b0 = (nt & 1) + (nt >> 1) * 4;
                    mma16816(acc[mi][nt][0], acc[mi][nt][1], acc[mi][nt][2], acc[mi][nt][3],
                             ah[mi][0], ah[mi][1], ah[mi][2], ah[mi][3],
                             bh[b0], bh[b0 + 2]);
                }
            // term 2: Wl * X (lo limb at hi address ^ 64)
#pragma unroll
            for (int mi = 0; mi < 4; ++mi) {
                uint32_t al[4];
                ldsm4(al[0], al[1], al[2], al[3],
                      (aB[kh] + so + mi * 2048) ^ 64u);
#pragma unroll
                for (int nt = 0; nt < 4; ++nt) {
                    const int b0 = (nt & 1) + (nt >> 1) * 4;
                    mma16816(acc[mi][nt][0], acc[mi][nt][1], acc[mi][nt][2], acc[mi][nt][3],
                             al[0], al[1], al[2], al[3],
                             bh[b0], bh[b0 + 2]);
                }
            }
        }
    };

    // prologue: steps 0,1 -> stages 0,1
    issue(0);              CP_COMMIT();
    issue(STAGE_STRIDE);   CP_COMMIT();

    // main: 733 x 3 steps, stage offsets compile-time
    for (int i = 0; i < 733; ++i) {
#pragma unroll
        for (int u = 0; u < 3; ++u) {
            CP_WAIT(1);
            __syncthreads();
            const int s = 3 * i + u;
            if (s + 2 < NSTEP)
                issue((uint32_t)(((u + 2) % 3) * STAGE_STRIDE));
            CP_COMMIT();
            compute((uint32_t)(u * STAGE_STRIDE));
        }
    }
    // tail: step 2199 -> stage 0
    CP_WAIT(0);
    __syncthreads();
    compute(0);

    // ---- epilogue: stores + BN stats ----
    const int lg = l >> 2;
    const int lc = l & 3;
    const int orow = i0 + ((w & 3) >> 1);
    const int jb   = (w & 1) * 32;

#pragma unroll
    for (int mi = 0; mi < 4; ++mi) {
#pragma unroll
        for (int h = 0; h < 2; ++h) {
            const int m = mbase + mrow0 + mi * 16 + lg + h * 8;
            float* rowp = out + (((size_t)(b * 256 + m)) * 64 + orow) * 64 + jb + 2 * lc;
            float s = 0.f, sq = 0.f;
#pragma unroll
            for (int nt = 0; nt < 4; ++nt) {
                float c0 = acc[mi][nt][2 * h];
                float c1 = acc[mi][nt][2 * h + 1];
                reinterpret_cast<float2*>(rowp + nt * 8)[0] = make_float2(c0, c1);
                s  += c0 + c1;
                sq += c0 * c0 + c1 * c1;
            }
            s  += __shfl_xor_sync(0xffffffffu, s,  1);
            s  += __shfl_xor_sync(0xffffffffu, s,  2);
            sq += __shfl_xor_sync(0xffffffffu, sq, 1);
            sq += __shfl_xor_sync(0xffffffffu, sq, 2);
            if (lc == 0) {
                atomicAdd(&g_sum[m], s);
                atomicAdd(&g_sqsum[m], sq);
            }
        }
    }
}

// ---------------- BN normalize ----------------
__global__ void bn_kernel(float* __restrict__ out,
                          const float* __restrict__ gamma,
                          const float* __restrict__ beta)
{
    const long total4 = (long)Bn * COUTc * Hdim * Wdim / 4;
    long i4 = (long)blockIdx.x * blockDim.x + threadIdx.x;
    if (i4 >= total4) return;
    int c = (int)(i4 >> 10) & (COUTc - 1);
    const float invN = 1.0f / (float)(Bn * Hdim * Wdim);
    float mean  = g_sum[c] * invN;
    float var   = g_sqsum[c] * invN - mean * mean;
    float scale = gamma[c] * rsqrtf(var + 1e-5f);
    float shift = beta[c] - mean * scale;
    float4 v = reinterpret_cast<float4*>(out)[i4];
    v.x = v.x * scale + shift;
    v.y = v.y * scale + shift;
    v.z = v.z * scale + shift;
    v.w = v.w * scale + shift;
    reinterpret_cast<float4*>(out)[i4] = v;
}

// ---------------- launch ----------------
extern "C" void kernel_launch(void* const* d_in, const int* in_sizes, int n_in,
                              void* d_out, int out_size)
{
    const float* x     = (const float*)d_in[0];
    const float* w     = (const float*)d_in[1];
    const float* gamma = (const float*)d_in[2];
    const float* beta  = (const float*)d_in[3];
    float* out = (float*)d_out;

    cudaFuncSetAttribute(gemm_kernel, cudaFuncAttributeMaxDynamicSharedMemorySize,
                         SMEM_TOTAL);

    prep_w_kernel<<<70400, 256>>>(w);
    prep_x_kernel<<<65280, 256>>>(x);
    zero_stats_kernel<<<1, 256>>>();

    dim3 grid(2, 256);
    gemm_kernel<<<grid, 256, SMEM_TOTAL>>>(out);

    const long total4 = (long)Bn * COUTc * Hdim * Wdim / 4;
    bn_kernel<<<(unsigned)((total4 + 255) / 256), 256>>>(out, gamma, beta);
}

// round 10
// speedup vs baseline: 9.1647x; 2.1433x over previous
#include <cuda_runtime.h>
#include <cuda_fp16.h>
#include <stdint.h>

// ---------------- problem constants ----------------
#define Bn    8
#define CINc  256
#define COUTc 256
#define Hdim  64
#define Wdim  64
#define HP    120
#define WP    68
#define NTAP  275
#define NSTEP 1100     // 275 taps * 4 ci-chunks of 64

// ---------------- smem ----------------
#define OFF_B        16384
#define STAGE_STRIDE 32768          // A 16KB + B 16KB
#define SMEM_TOTAL   (STAGE_STRIDE * 3)    // 96KB -> 2 CTAs/SM

// ---------------- device scratch ----------------
__device__ __align__(256) __half g_xq[(size_t)Bn * HP * WP * CINc];   // x fp16
__device__ __align__(256) __half g_wq[(size_t)NTAP * COUTc * CINc];   // w fp16
__device__ float g_sum[COUTc];
__device__ float g_sqsum[COUTc];

// ---------------- PTX helpers ----------------
__device__ __forceinline__ uint32_t smem_u32(const void* p) {
    uint32_t a;
    asm("{ .reg .u64 t; cvta.to.shared.u64 t, %1; cvt.u32.u64 %0, t; }"
        : "=r"(a) : "l"(p));
    return a;
}
__device__ __forceinline__ void cp16(uint32_t dst, const void* src) {
    asm volatile("cp.async.cg.shared.global [%0], [%1], 16;"
                 :: "r"(dst), "l"(src) : "memory");
}
#define CP_COMMIT() asm volatile("cp.async.commit_group;" ::: "memory")
#define CP_WAIT(n)  asm volatile("cp.async.wait_group %0;" :: "n"(n) : "memory")

__device__ __forceinline__ void ldsm4(uint32_t& r0, uint32_t& r1,
                                      uint32_t& r2, uint32_t& r3, uint32_t a) {
    asm volatile("ldmatrix.sync.aligned.m8n8.x4.shared.b16 {%0,%1,%2,%3}, [%4];"
                 : "=r"(r0), "=r"(r1), "=r"(r2), "=r"(r3) : "r"(a));
}
__device__ __forceinline__ void mma16816(float& d0, float& d1, float& d2, float& d3,
                                         uint32_t a0, uint32_t a1, uint32_t a2, uint32_t a3,
                                         uint32_t b0, uint32_t b1) {
    asm volatile("mma.sync.aligned.m16n8k16.row.col.f32.f16.f16.f32 "
                 "{%0,%1,%2,%3},{%4,%5,%6,%7},{%8,%9},{%0,%1,%2,%3};"
                 : "+f"(d0), "+f"(d1), "+f"(d2), "+f"(d3)
                 : "r"(a0), "r"(a1), "r"(a2), "r"(a3), "r"(b0), "r"(b1));
}

// ---------------- prep kernels ----------------
__global__ void prep_w_kernel(const float* __restrict__ w) {
    int idx = blockIdx.x * 256 + threadIdx.x;
    int ci  = idx & 255;
    int co  = (idx >> 8) & 255;
    int tap = idx >> 16;
    int t = tap / 5, kw = tap - 5 * t;
    int ik = t / 5,  kh = t - 5 * ik;
    g_wq[idx] = __float2half(
        w[(((size_t)(co * 11 + ik) * 256 + ci) * 25) + kh * 5 + kw]);
}

__global__ void prep_x_kernel(const float* __restrict__ x) {
    int idx = blockIdx.x * 256 + threadIdx.x;
    int ci   = idx & 255;
    int rest = idx >> 8;
    int wp = rest % WP;
    int r2 = rest / WP;
    int hp = r2 % HP;
    int b  = r2 / HP;
    int h = hp - 25, wq = wp - 2;
    float v = 0.f;
    if ((unsigned)h < 64u && (unsigned)wq < 64u)
        v = x[(((size_t)(b * 256 + ci) * 64) + h) * 64 + wq];
    g_xq[idx] = __float2half(v);
}

__global__ void zero_stats_kernel() {
    int t = threadIdx.x;
    if (t < COUTc) { g_sum[t] = 0.f; g_sqsum[t] = 0.f; }
}

// ---------------- main GEMM kernel (256 thr, 2 CTAs/SM) ----------------
__global__ __launch_bounds__(256, 2)
void gemm_kernel(float* __restrict__ out)
{
    extern __shared__ __align__(1024) char smem[];
    const uint32_t sb = smem_u32(smem);

    const int tid  = threadIdx.x;
    const int w    = tid >> 5;
    const int l    = tid & 31;
    const int mbase = blockIdx.x * 128;
    const int nblk  = blockIdx.y;
    const int b     = nblk >> 5;
    const int i0    = (nblk & 31) * 2;

    // ---- copy geometry (A and B tiles both [128 rows][128B], K=64) ----
    const int cA  = tid & 7;                 // 16B chunk (8 ci each) within 64-ci slice
    const int rA0 = tid >> 3;                // rows rA0 + 32k
    const uint32_t swc = 16u * (uint32_t)(cA ^ (rA0 & 7));
    const uint32_t adst = sb + (uint32_t)rA0 * 128 + swc;

    const __half* aptr = g_wq + (size_t)(mbase + rA0) * 256 + (size_t)cA * 8;
    const __half* xptr = g_xq + (size_t)b * (HP * WP * 256)
                       + ((size_t)i0 * WP + rA0) * 256 + (size_t)cA * 8;
    int ac4 = 0;     // A: every 4th step jumps a tap
    int xc20 = 0;    // X: every 20th step jumps a t-row

    // ---- mma geometry ----
    const int mrow0 = (w >> 2) * 64;
    const int nrow0 = (w & 3) * 32;
    const uint32_t swz = (uint32_t)(l & 7);
    const uint32_t hl  = (uint32_t)(l >> 4);
    const uint32_t aLaneOff = (uint32_t)(mrow0 + (l & 15)) * 128;
    const uint32_t bLaneOff = (uint32_t)(nrow0 + (l & 7) + ((l >> 3) & 1) * 8) * 128;

    // Precomputed ldsm bases per k16-group (4 groups of K=64); sb folded once.
    uint32_t aB[4], bB[4];
#pragma unroll
    for (int kh = 0; kh < 4; ++kh) {
        const uint32_t ch = 2u * kh + hl;
        aB[kh] = sb + aLaneOff + 16u * (ch ^ swz);
        bB[kh] = sb + OFF_B + bLaneOff + 16u * (ch ^ swz);
    }

    float acc[4][4][4];
#pragma unroll
    for (int mi = 0; mi < 4; ++mi)
#pragma unroll
        for (int nt = 0; nt < 4; ++nt)
#pragma unroll
            for (int r = 0; r < 4; ++r) acc[mi][nt][r] = 0.f;

    // ---- issue one 32KB stage (A 16KB + B 16KB) ----
    auto issue = [&](const uint32_t so) {
#pragma unroll
        for (int k = 0; k < 4; ++k)
            cp16(so + adst + k * 4096, aptr + k * 8192);         // A rows rA0+32k
        cp16(so + adst + OFF_B,         xptr);                    // B n-rows:
        cp16(so + adst + OFF_B + 4096,  xptr + 8192);             //  orow0: j=rA0, rA0+32
        cp16(so + adst + OFF_B + 8192,  xptr + 17408);            //  orow1: j=rA0, rA0+32
        cp16(so + adst + OFF_B + 12288, xptr + 25600);
        aptr += (ac4 == 3) ? 65344 : 64;      // 65536 - 192
        ac4 = (ac4 + 1) & 3;
        xptr += (xc20 == 19) ? 16192 : 64;    // 17408 - 1024 - 192
        xc20 = (xc20 == 19) ? 0 : xc20 + 1;
    };

    // ---- compute one step (stage offset literal) ----
    auto compute = [&](const uint32_t so) {
#pragma unroll
        for (int kh = 0; kh < 4; ++kh) {
            uint32_t bh[8], ah[4][4];
            ldsm4(bh[0], bh[1], bh[2], bh[3], bB[kh] + so);
            ldsm4(bh[4], bh[5], bh[6], bh[7], bB[kh] + so + 2048);
#pragma unroll
            for (int mi = 0; mi < 4; ++mi)
                ldsm4(ah[mi][0], ah[mi][1], ah[mi][2], ah[mi][3],
                      aB[kh] + so + mi * 2048);
            // ldsm4 reg order r0={nLO,kLO} r1={nHI,kLO} r2={nLO,kHI} r3={nHI,kHI}
            // mma {b0,b1} = {kLO,kHI} of one n-group: b0=(nt&1)+(nt>>1)*4, b1=b0+2.
#pragma unroll
            for (int mi = 0; mi < 4; ++mi)
#pragma unroll
                for (int nt = 0; nt < 4; ++nt) {
                    const int b0 = (nt & 1) + (nt >> 1) * 4;
                    mma16816(acc[mi][nt][0], acc[mi][nt][1], acc[mi][nt][2], acc[mi][nt][3],
                             ah[mi][0], ah[mi][1], ah[mi][2], ah[mi][3],
                             bh[b0], bh[b0 + 2]);
                }
        }
    };

    // prologue: steps 0,1 -> stages 0,1
    issue(0);              CP_COMMIT();
    issue(STAGE_STRIDE);   CP_COMMIT();

    // main: 366 x 3 steps = 1098, stage offsets compile-time
    for (int i = 0; i < 366; ++i) {
#pragma unroll
        for (int u = 0; u < 3; ++u) {
            CP_WAIT(1);
            __syncthreads();
            issue((uint32_t)(((u + 2) % 3) * STAGE_STRIDE));   // for step s+2 (max 1099)
            CP_COMMIT();
            compute((uint32_t)(u * STAGE_STRIDE));
        }
    }
    // tail: steps 1098 (stage 0), 1099 (stage 1)
    CP_WAIT(1);
    __syncthreads();
    compute(0);
    CP_WAIT(0);
    __syncthreads();
    compute(STAGE_STRIDE);

    // ---- epilogue: stores + BN stats ----
    const int lg = l >> 2;
    const int lc = l & 3;
    const int orow = i0 + ((w & 3) >> 1);
    const int jb   = (w & 1) * 32;

#pragma unroll
    for (int mi = 0; mi < 4; ++mi) {
#pragma unroll
        for (int h = 0; h < 2; ++h) {
            const int m = mbase + mrow0 + mi * 16 + lg + h * 8;
            float* rowp = out + (((size_t)(b * 256 + m)) * 64 + orow) * 64 + jb + 2 * lc;
            float s = 0.f, sq = 0.f;
#pragma unroll
            for (int nt = 0; nt < 4; ++nt) {
                float c0 = acc[mi][nt][2 * h];
                float c1 = acc[mi][nt][2 * h + 1];
                reinterpret_cast<float2*>(rowp + nt * 8)[0] = make_float2(c0, c1);
                s  += c0 + c1;
                sq += c0 * c0 + c1 * c1;
            }
            s  += __shfl_xor_sync(0xffffffffu, s,  1);
            s  += __shfl_xor_sync(0xffffffffu, s,  2);
            sq += __shfl_xor_sync(0xffffffffu, sq, 1);
            sq += __shfl_xor_sync(0xffffffffu, sq, 2);
            if (lc == 0) {
                atomicAdd(&g_sum[m], s);
                atomicAdd(&g_sqsum[m], sq);
            }
        }
    }
}

// ---------------- BN normalize ----------------
__global__ void bn_kernel(float* __restrict__ out,
                          const float* __restrict__ gamma,
                          const float* __restrict__ beta)
{
    const long total4 = (long)Bn * COUTc * Hdim * Wdim / 4;
    long i4 = (long)blockIdx.x * blockDim.x + threadIdx.x;
    if (i4 >= total4) return;
    int c = (int)(i4 >> 10) & (COUTc - 1);
    const float invN = 1.0f / (float)(Bn * Hdim * Wdim);
    float mean  = g_sum[c] * invN;
    float var   = g_sqsum[c] * invN - mean * mean;
    float scale = gamma[c] * rsqrtf(var + 1e-5f);
    float shift = beta[c] - mean * scale;
    float4 v = reinterpret_cast<float4*>(out)[i4];
    v.x = v.x * scale + shift;
    v.y = v.y * scale + shift;
    v.z = v.z * scale + shift;
    v.w = v.w * scale + shift;
    reinterpret_cast<float4*>(out)[i4] = v;
}

// ---------------- launch ----------------
extern "C" void kernel_launch(void* const* d_in, const int* in_sizes, int n_in,
                              void* d_out, int out_size)
{
    const float* x     = (const float*)d_in[0];
    const float* w     = (const float*)d_in[1];
    const float* gamma = (const float*)d_in[2];
    const float* beta  = (const float*)d_in[3];
    float* out = (float*)d_out;

    cudaFuncSetAttribute(gemm_kernel, cudaFuncAttributeMaxDynamicSharedMemorySize,
                         SMEM_TOTAL);

    prep_w_kernel<<<70400, 256>>>(w);
    prep_x_kernel<<<65280, 256>>>(x);
    zero_stats_kernel<<<1, 256>>>();

    dim3 grid(2, 256);
    gemm_kernel<<<grid, 256, SMEM_TOTAL>>>(out);

    const long total4 = (long)Bn * COUTc * Hdim * Wdim / 4;
    bn_kernel<<<(unsigned)((total4 + 255) / 256), 256>>>(out, gamma, beta);
}

// round 11
// speedup vs baseline: 9.2105x; 1.0050x over previous
#include <cuda_runtime.h>
#include <cuda_fp16.h>
#include <stdint.h>

// ---------------- problem constants ----------------
#define Bn    8
#define CINc  256
#define COUTc 256
#define Hdim  64
#define Wdim  64
#define HP    120
#define WP    68
#define NTAP  275
#define NSTEP 1100     // 275 taps * 4 ci-chunks of 64

// ---------------- smem ----------------
#define OFF_B        16384
#define STAGE_STRIDE 32768          // A 16KB + B 16KB
#define SMEM_TOTAL   (STAGE_STRIDE * 3)    // 96KB -> 2 CTAs/SM

// ---------------- device scratch ----------------
__device__ __align__(256) __half g_xq[(size_t)Bn * HP * WP * CINc];   // x fp16
__device__ __align__(256) __half g_wq[(size_t)NTAP * COUTc * CINc];   // w fp16
__device__ float g_sum[COUTc];
__device__ float g_sqsum[COUTc];

// ---------------- PTX helpers ----------------
__device__ __forceinline__ uint32_t smem_u32(const void* p) {
    uint32_t a;
    asm("{ .reg .u64 t; cvta.to.shared.u64 t, %1; cvt.u32.u64 %0, t; }"
        : "=r"(a) : "l"(p));
    return a;
}
__device__ __forceinline__ void cp16(uint32_t dst, const void* src) {
    asm volatile("cp.async.cg.shared.global [%0], [%1], 16;"
                 :: "r"(dst), "l"(src) : "memory");
}
#define CP_COMMIT() asm volatile("cp.async.commit_group;" ::: "memory")
#define CP_WAIT(n)  asm volatile("cp.async.wait_group %0;" :: "n"(n) : "memory")

__device__ __forceinline__ void ldsm4(uint32_t& r0, uint32_t& r1,
                                      uint32_t& r2, uint32_t& r3, uint32_t a) {
    asm volatile("ldmatrix.sync.aligned.m8n8.x4.shared.b16 {%0,%1,%2,%3}, [%4];"
                 : "=r"(r0), "=r"(r1), "=r"(r2), "=r"(r3) : "r"(a));
}
__device__ __forceinline__ void mma16816(float& d0, float& d1, float& d2, float& d3,
                                         uint32_t a0, uint32_t a1, uint32_t a2, uint32_t a3,
                                         uint32_t b0, uint32_t b1) {
    asm volatile("mma.sync.aligned.m16n8k16.row.col.f32.f16.f16.f32 "
                 "{%0,%1,%2,%3},{%4,%5,%6,%7},{%8,%9},{%0,%1,%2,%3};"
                 : "+f"(d0), "+f"(d1), "+f"(d2), "+f"(d3)
                 : "r"(a0), "r"(a1), "r"(a2), "r"(a3), "r"(b0), "r"(b1));
}

// ---------------- prep kernels ----------------
__global__ void prep_w_kernel(const float* __restrict__ w) {
    int idx = blockIdx.x * 256 + threadIdx.x;
    int ci  = idx & 255;
    int co  = (idx >> 8) & 255;
    int tap = idx >> 16;
    int t = tap / 5, kw = tap - 5 * t;
    int ik = t / 5,  kh = t - 5 * ik;
    g_wq[idx] = __float2half(
        w[(((size_t)(co * 11 + ik) * 256 + ci) * 25) + kh * 5 + kw]);
}

__global__ void prep_x_kernel(const float* __restrict__ x) {
    int idx = blockIdx.x * 256 + threadIdx.x;
    int ci   = idx & 255;
    int rest = idx >> 8;
    int wp = rest % WP;
    int r2 = rest / WP;
    int hp = r2 % HP;
    int b  = r2 / HP;
    int h = hp - 25, wq = wp - 2;
    float v = 0.f;
    if ((unsigned)h < 64u && (unsigned)wq < 64u)
        v = x[(((size_t)(b * 256 + ci) * 64) + h) * 64 + wq];
    g_xq[idx] = __float2half(v);
}

__global__ void zero_stats_kernel() {
    int t = threadIdx.x;
    if (t < COUTc) { g_sum[t] = 0.f; g_sqsum[t] = 0.f; }
}

// ---------------- main GEMM kernel (128 thr, 4 warps of 64x64, 2 CTAs/SM) ----------------
__global__ __launch_bounds__(128, 2)
void gemm_kernel(float* __restrict__ out)
{
    extern __shared__ __align__(1024) char smem[];
    const uint32_t sb = smem_u32(smem);

    const int tid  = threadIdx.x;
    const int w    = tid >> 5;               // 4 warps: 2m x 2n
    const int l    = tid & 31;
    const int mbase = blockIdx.x * 128;
    const int nblk  = blockIdx.y;
    const int b     = nblk >> 5;
    const int i0    = (nblk & 31) * 2;

    // ---- copy geometry: 8 A-rows + 8 B-rows per thread, 16B each ----
    const int cA  = tid & 7;                 // 16B chunk within 128B row
    const int rA0 = tid >> 3;                // 0..15; rows rA0 + 16k, k<8
    const uint32_t swc = 16u * (uint32_t)(cA ^ (rA0 & 7));   // 16k%8==0 -> swizzle row-invariant
    const uint32_t adst = sb + (uint32_t)rA0 * 128 + swc;

    const __half* aptr = g_wq + (size_t)(mbase + rA0) * 256 + (size_t)cA * 8;
    const __half* xptr = g_xq + (size_t)b * (HP * WP * 256)
                       + ((size_t)i0 * WP + rA0) * 256 + (size_t)cA * 8;
    int ac4 = 0;     // A: every 4th step jumps a tap
    int xc20 = 0;    // X: every 20th step jumps a t-row

    // ---- mma geometry: warp tile 64x64 ----
    const int mrow0 = (w >> 1) * 64;
    const int nrow0 = (w & 1) * 64;
    const uint32_t swz = (uint32_t)(l & 7);
    const uint32_t hl  = (uint32_t)(l >> 4);
    const uint32_t aLaneOff = (uint32_t)(mrow0 + (l & 15)) * 128;
    const uint32_t bLaneOff = (uint32_t)(nrow0 + (l & 7) + ((l >> 3) & 1) * 8) * 128;

    uint32_t aB[4], bB[4];
#pragma unroll
    for (int kh = 0; kh < 4; ++kh) {
        const uint32_t ch = 2u * kh + hl;
        aB[kh] = sb + aLaneOff + 16u * (ch ^ swz);
        bB[kh] = sb + OFF_B + bLaneOff + 16u * (ch ^ swz);
    }

    float acc[4][8][4];
#pragma unroll
    for (int mi = 0; mi < 4; ++mi)
#pragma unroll
        for (int nj = 0; nj < 8; ++nj)
#pragma unroll
            for (int r = 0; r < 4; ++r) acc[mi][nj][r] = 0.f;

    // ---- issue one 32KB stage (A 16KB + B 16KB), 16 cp16 per thread ----
    auto issue = [&](const uint32_t so) {
#pragma unroll
        for (int k = 0; k < 8; ++k)
            cp16(so + adst + k * 2048, aptr + k * 4096);       // A rows rA0+16k
        // B rows rA0+16k: orow = k>>2, j = rA0 + 16(k&3)
#pragma unroll
        for (int k = 0; k < 8; ++k)
            cp16(so + adst + OFF_B + k * 2048,
                 xptr + (k >> 2) * 17408 + (k & 3) * 4096);
        aptr += (ac4 == 3) ? 65344 : 64;      // next tap: +65536-192
        ac4 = (ac4 + 1) & 3;
        xptr += (xc20 == 19) ? 16192 : 64;    // next t-row: +17408-1216
        xc20 = (xc20 == 19) ? 0 : xc20 + 1;
    };

    // ---- compute one step (stage offset literal) ----
    auto compute = [&](const uint32_t so) {
#pragma unroll
        for (int kh = 0; kh < 4; ++kh) {
            uint32_t bf[4][4], ah[4][4];
#pragma unroll
            for (int ni = 0; ni < 4; ++ni)
                ldsm4(bf[ni][0], bf[ni][1], bf[ni][2], bf[ni][3],
                      bB[kh] + so + ni * 2048);
#pragma unroll
            for (int mi = 0; mi < 4; ++mi)
                ldsm4(ah[mi][0], ah[mi][1], ah[mi][2], ah[mi][3],
                      aB[kh] + so + mi * 2048);
            // ldsm4 reg order r0={n8lo,kLO} r1={n8hi,kLO} r2={n8lo,kHI} r3={n8hi,kHI}
            // per n16-group ni: n8lo -> {bf[ni][0],bf[ni][2]}, n8hi -> {bf[ni][1],bf[ni][3]}
#pragma unroll
            for (int mi = 0; mi < 4; ++mi)
#pragma unroll
                for (int ni = 0; ni < 4; ++ni) {
                    mma16816(acc[mi][2*ni][0], acc[mi][2*ni][1],
                             acc[mi][2*ni][2], acc[mi][2*ni][3],
                             ah[mi][0], ah[mi][1], ah[mi][2], ah[mi][3],
                             bf[ni][0], bf[ni][2]);
                    mma16816(acc[mi][2*ni+1][0], acc[mi][2*ni+1][1],
                             acc[mi][2*ni+1][2], acc[mi][2*ni+1][3],
                             ah[mi][0], ah[mi][1], ah[mi][2], ah[mi][3],
                             bf[ni][1], bf[ni][3]);
                }
        }
    };

    // prologue: steps 0,1 -> stages 0,1
    issue(0);              CP_COMMIT();
    issue(STAGE_STRIDE);   CP_COMMIT();

    // main: 366 x 3 steps = 1098, stage offsets compile-time
    for (int i = 0; i < 366; ++i) {
#pragma unroll
        for (int u = 0; u < 3; ++u) {
            CP_WAIT(1);
            __syncthreads();
            issue((uint32_t)(((u + 2) % 3) * STAGE_STRIDE));
            CP_COMMIT();
            compute((uint32_t)(u * STAGE_STRIDE));
        }
    }
    // tail: steps 1098 (stage 0), 1099 (stage 1)
    CP_WAIT(1);
    __syncthreads();
    compute(0);
    CP_WAIT(0);
    __syncthreads();
    compute(STAGE_STRIDE);

    // ---- epilogue: stores + BN stats ----
    const int lg = l >> 2;
    const int lc = l & 3;
    const int orow = i0 + (w & 1);

#pragma unroll
    for (int mi = 0; mi < 4; ++mi) {
#pragma unroll
        for (int h = 0; h < 2; ++h) {
            const int m = mbase + mrow0 + mi * 16 + lg + h * 8;
            float* rowp = out + (((size_t)(b * 256 + m)) * 64 + orow) * 64 + 2 * lc;
            float s = 0.f, sq = 0.f;
#pragma unroll
            for (int nj = 0; nj < 8; ++nj) {
                float c0 = acc[mi][nj][2 * h];
                float c1 = acc[mi][nj][2 * h + 1];
                reinterpret_cast<float2*>(rowp + nj * 8)[0] = make_float2(c0, c1);
                s  += c0 + c1;
                sq += c0 * c0 + c1 * c1;
            }
            s  += __shfl_xor_sync(0xffffffffu, s,  1);
            s  += __shfl_xor_sync(0xffffffffu, s,  2);
            sq += __shfl_xor_sync(0xffffffffu, sq, 1);
            sq += __shfl_xor_sync(0xffffffffu, sq, 2);
            if (lc == 0) {
                atomicAdd(&g_sum[m], s);
                atomicAdd(&g_sqsum[m], sq);
            }
        }
    }
}

// ---------------- BN normalize ----------------
__global__ void bn_kernel(float* __restrict__ out,
                          const float* __restrict__ gamma,
                          const float* __restrict__ beta)
{
    const long total4 = (long)Bn * COUTc * Hdim * Wdim / 4;
    long i4 = (long)blockIdx.x * blockDim.x + threadIdx.x;
    if (i4 >= total4) return;
    int c = (int)(i4 >> 10) & (COUTc - 1);
    const float invN = 1.0f / (float)(Bn * Hdim * Wdim);
    float mean  = g_sum[c] * invN;
    float var   = g_sqsum[c] * invN - mean * mean;
    float scale = gamma[c] * rsqrtf(var + 1e-5f);
    float shift = beta[c] - mean * scale;
    float4 v = reinterpret_cast<float4*>(out)[i4];
    v.x = v.x * scale + shift;
    v.y = v.y * scale + shift;
    v.z = v.z * scale + shift;
    v.w = v.w * scale + shift;
    reinterpret_cast<float4*>(out)[i4] = v;
}

// ---------------- launch ----------------
extern "C" void kernel_launch(void* const* d_in, const int* in_sizes, int n_in,
                              void* d_out, int out_size)
{
    const float* x     = (const float*)d_in[0];
    const float* w     = (const float*)d_in[1];
    const float* gamma = (const float*)d_in[2];
    const float* beta  = (const float*)d_in[3];
    float* out = (float*)d_out;

    cudaFuncSetAttribute(gemm_kernel, cudaFuncAttributeMaxDynamicSharedMemorySize,
                         SMEM_TOTAL);

    prep_w_kernel<<<70400, 256>>>(w);
    prep_x_kernel<<<65280, 256>>>(x);
    zero_stats_kernel<<<1, 256>>>();

    dim3 grid(2, 256);                 // 512 CTAs of 128 threads, 2 per SM
    gemm_kernel<<<grid, 128, SMEM_TOTAL>>>(out);

    const long total4 = (long)Bn * COUTc * Hdim * Wdim / 4;
    bn_kernel<<<(unsigned)((total4 + 255) / 256), 256>>>(out, gamma, beta);
}

// round 12
// speedup vs baseline: 9.3123x; 1.0110x over previous
#include <cuda_runtime.h>
#include <cuda_fp16.h>
#include <stdint.h>

// ---------------- problem constants ----------------
#define Bn    8
#define CINc  256
#define COUTc 256
#define Hdim  64
#define Wdim  64
#define HP    120
#define WP    68
#define NTAP  275
#define NSTEP 1100     // 275 taps * 4 ci-chunks of 64

// ---------------- smem ----------------
#define OFF_B        16384
#define STAGE_STRIDE 32768          // A 16KB + B 16KB
#define SMEM_TOTAL   (STAGE_STRIDE * 3)    // 96KB -> 2 CTAs/SM

// ---------------- device scratch ----------------
__device__ __align__(256) __half g_xq[(size_t)Bn * HP * WP * CINc];   // x fp16
__device__ __align__(256) __half g_wq[(size_t)NTAP * COUTc * CINc];   // w fp16
__device__ float g_sum[COUTc];
__device__ float g_sqsum[COUTc];

// ---------------- PTX helpers ----------------
__device__ __forceinline__ uint32_t smem_u32(const void* p) {
    uint32_t a;
    asm("{ .reg .u64 t; cvta.to.shared.u64 t, %1; cvt.u32.u64 %0, t; }"
        : "=r"(a) : "l"(p));
    return a;
}
__device__ __forceinline__ void cp16(uint32_t dst, const void* src) {
    asm volatile("cp.async.cg.shared.global [%0], [%1], 16;"
                 :: "r"(dst), "l"(src) : "memory");
}
#define CP_COMMIT() asm volatile("cp.async.commit_group;" ::: "memory")
#define CP_WAIT(n)  asm volatile("cp.async.wait_group %0;" :: "n"(n) : "memory")

__device__ __forceinline__ void ldsm4(uint32_t& r0, uint32_t& r1,
                                      uint32_t& r2, uint32_t& r3, uint32_t a) {
    asm volatile("ldmatrix.sync.aligned.m8n8.x4.shared.b16 {%0,%1,%2,%3}, [%4];"
                 : "=r"(r0), "=r"(r1), "=r"(r2), "=r"(r3) : "r"(a));
}
__device__ __forceinline__ void mma16816(float& d0, float& d1, float& d2, float& d3,
                                         uint32_t a0, uint32_t a1, uint32_t a2, uint32_t a3,
                                         uint32_t b0, uint32_t b1) {
    asm volatile("mma.sync.aligned.m16n8k16.row.col.f32.f16.f16.f32 "
                 "{%0,%1,%2,%3},{%4,%5,%6,%7},{%8,%9},{%0,%1,%2,%3};"
                 : "+f"(d0), "+f"(d1), "+f"(d2), "+f"(d3)
                 : "r"(a0), "r"(a1), "r"(a2), "r"(a3), "r"(b0), "r"(b1));
}

// ---------------- prep kernels ----------------
__global__ void prep_w_kernel(const float* __restrict__ w) {
    int idx = blockIdx.x * 256 + threadIdx.x;
    int ci  = idx & 255;
    int co  = (idx >> 8) & 255;
    int tap = idx >> 16;
    int t = tap / 5, kw = tap - 5 * t;
    int ik = t / 5,  kh = t - 5 * ik;
    g_wq[idx] = __float2half(
        w[(((size_t)(co * 11 + ik) * 256 + ci) * 25) + kh * 5 + kw]);
}

__global__ void prep_x_kernel(const float* __restrict__ x) {
    int idx = blockIdx.x * 256 + threadIdx.x;
    int ci   = idx & 255;
    int rest = idx >> 8;
    int wp = rest % WP;
    int r2 = rest / WP;
    int hp = r2 % HP;
    int b  = r2 / HP;
    int h = hp - 25, wq = wp - 2;
    float v = 0.f;
    if ((unsigned)h < 64u && (unsigned)wq < 64u)
        v = x[(((size_t)(b * 256 + ci) * 64) + h) * 64 + wq];
    g_xq[idx] = __float2half(v);
}

__global__ void zero_stats_kernel() {
    int t = threadIdx.x;
    if (t < COUTc) { g_sum[t] = 0.f; g_sqsum[t] = 0.f; }
}

// ---- fragment load / mma macros (explicit buffers, compile-time indices) ----
#define LDFRAGS(BF, AH, KH, SO) do {                                               \
    _Pragma("unroll")                                                              \
    for (int ni = 0; ni < 4; ++ni)                                                 \
        ldsm4(BF[ni][0], BF[ni][1], BF[ni][2], BF[ni][3],                          \
              bB[KH] + (SO) + ni * 2048);                                          \
    _Pragma("unroll")                                                              \
    for (int mi = 0; mi < 4; ++mi)                                                 \
        ldsm4(AH[mi][0], AH[mi][1], AH[mi][2], AH[mi][3],                          \
              aB[KH] + (SO) + mi * 2048);                                          \
} while (0)

#define MMAS(BF, AH) do {                                                          \
    _Pragma("unroll")                                                              \
    for (int mi = 0; mi < 4; ++mi)                                                 \
        _Pragma("unroll")                                                          \
        for (int ni = 0; ni < 4; ++ni) {                                           \
            mma16816(acc[mi][2*ni][0], acc[mi][2*ni][1],                           \
                     acc[mi][2*ni][2], acc[mi][2*ni][3],                           \
                     AH[mi][0], AH[mi][1], AH[mi][2], AH[mi][3],                   \
                     BF[ni][0], BF[ni][2]);                                        \
            mma16816(acc[mi][2*ni+1][0], acc[mi][2*ni+1][1],                       \
                     acc[mi][2*ni+1][2], acc[mi][2*ni+1][3],                       \
                     AH[mi][0], AH[mi][1], AH[mi][2], AH[mi][3],                   \
                     BF[ni][1], BF[ni][3]);                                        \
        }                                                                          \
} while (0)

// One pipelined step: kh0 ldsm first (tensor-ready ASAP), then cp.async issue,
// then frag-double-buffered kh loop (load kh+1 while kh's MMAs run).
#define STEP(SO, ISSUE_STMT) do {                                                  \
    LDFRAGS(bf0, ah0, 0, SO);                                                      \
    ISSUE_STMT;                                                                    \
    LDFRAGS(bf1, ah1, 1, SO);                                                      \
    MMAS(bf0, ah0);                                                                \
    LDFRAGS(bf0, ah0, 2, SO);                                                      \
    MMAS(bf1, ah1);                                                                \
    LDFRAGS(bf1, ah1, 3, SO);                                                      \
    MMAS(bf0, ah0);                                                                \
    MMAS(bf1, ah1);                                                                \
} while (0)

// ---------------- main GEMM kernel (128 thr, 4 warps of 64x64, 2 CTAs/SM) ----------------
__global__ __launch_bounds__(128, 2)
void gemm_kernel(float* __restrict__ out)
{
    extern __shared__ __align__(1024) char smem[];
    const uint32_t sb = smem_u32(smem);

    const int tid  = threadIdx.x;
    const int w    = tid >> 5;               // 4 warps: 2m x 2n
    const int l    = tid & 31;
    const int mbase = blockIdx.x * 128;
    const int nblk  = blockIdx.y;
    const int b     = nblk >> 5;
    const int i0    = (nblk & 31) * 2;

    // ---- copy geometry: 8 A-rows + 8 B-rows per thread, 16B each ----
    const int cA  = tid & 7;
    const int rA0 = tid >> 3;                // 0..15; rows rA0 + 16k
    const uint32_t swc = 16u * (uint32_t)(cA ^ (rA0 & 7));
    const uint32_t adst = sb + (uint32_t)rA0 * 128 + swc;

    const __half* aptr = g_wq + (size_t)(mbase + rA0) * 256 + (size_t)cA * 8;
    const __half* xptr = g_xq + (size_t)b * (HP * WP * 256)
                       + ((size_t)i0 * WP + rA0) * 256 + (size_t)cA * 8;
    int ac4 = 0;
    int xc20 = 0;

    // ---- mma geometry: warp tile 64x64 ----
    const int mrow0 = (w >> 1) * 64;
    const int nrow0 = (w & 1) * 64;
    const uint32_t swz = (uint32_t)(l & 7);
    const uint32_t hl  = (uint32_t)(l >> 4);
    const uint32_t aLaneOff = (uint32_t)(mrow0 + (l & 15)) * 128;
    const uint32_t bLaneOff = (uint32_t)(nrow0 + (l & 7) + ((l >> 3) & 1) * 8) * 128;

    uint32_t aB[4], bB[4];
#pragma unroll
    for (int kh = 0; kh < 4; ++kh) {
        const uint32_t ch = 2u * kh + hl;
        aB[kh] = sb + aLaneOff + 16u * (ch ^ swz);
        bB[kh] = sb + OFF_B + bLaneOff + 16u * (ch ^ swz);
    }

    float acc[4][8][4];
#pragma unroll
    for (int mi = 0; mi < 4; ++mi)
#pragma unroll
        for (int nj = 0; nj < 8; ++nj)
#pragma unroll
            for (int r = 0; r < 4; ++r) acc[mi][nj][r] = 0.f;

    // double-buffered fragments
    uint32_t bf0[4][4], bf1[4][4], ah0[4][4], ah1[4][4];

    // ---- issue one 32KB stage (A 16KB + B 16KB), 16 cp16 per thread ----
    auto issue = [&](const uint32_t so) {
#pragma unroll
        for (int k = 0; k < 8; ++k)
            cp16(so + adst + k * 2048, aptr + k * 4096);
#pragma unroll
        for (int k = 0; k < 8; ++k)
            cp16(so + adst + OFF_B + k * 2048,
                 xptr + (k >> 2) * 17408 + (k & 3) * 4096);
        aptr += (ac4 == 3) ? 65344 : 64;
        ac4 = (ac4 + 1) & 3;
        xptr += (xc20 == 19) ? 16192 : 64;
        xc20 = (xc20 == 19) ? 0 : xc20 + 1;
    };

    // prologue: steps 0,1 -> stages 0,1
    issue(0);              CP_COMMIT();
    issue(STAGE_STRIDE);   CP_COMMIT();

    // main: 366 x 3 steps = 1098, stage offsets compile-time
    for (int i = 0; i < 366; ++i) {
        CP_WAIT(1);
        __syncthreads();
        STEP(0,                { issue(2 * STAGE_STRIDE); CP_COMMIT(); });
        CP_WAIT(1);
        __syncthreads();
        STEP(STAGE_STRIDE,     { issue(0);                CP_COMMIT(); });
        CP_WAIT(1);
        __syncthreads();
        STEP(2 * STAGE_STRIDE, { issue(STAGE_STRIDE);     CP_COMMIT(); });
    }
    // tails: steps 1098 (stage 0), 1099 (stage 1)
    CP_WAIT(1);
    __syncthreads();
    STEP(0, (void)0);
    CP_WAIT(0);
    __syncthreads();
    STEP(STAGE_STRIDE, (void)0);

    // ---- epilogue: stores + BN stats ----
    const int lg = l >> 2;
    const int lc = l & 3;
    const int orow = i0 + (w & 1);

#pragma unroll
    for (int mi = 0; mi < 4; ++mi) {
#pragma unroll
        for (int h = 0; h < 2; ++h) {
            const int m = mbase + mrow0 + mi * 16 + lg + h * 8;
            float* rowp = out + (((size_t)(b * 256 + m)) * 64 + orow) * 64 + 2 * lc;
            float s = 0.f, sq = 0.f;
#pragma unroll
            for (int nj = 0; nj < 8; ++nj) {
                float c0 = acc[mi][nj][2 * h];
                float c1 = acc[mi][nj][2 * h + 1];
                reinterpret_cast<float2*>(rowp + nj * 8)[0] = make_float2(c0, c1);
                s  += c0 + c1;
                sq += c0 * c0 + c1 * c1;
            }
            s  += __shfl_xor_sync(0xffffffffu, s,  1);
            s  += __shfl_xor_sync(0xffffffffu, s,  2);
            sq += __shfl_xor_sync(0xffffffffu, sq, 1);
            sq += __shfl_xor_sync(0xffffffffu, sq, 2);
            if (lc == 0) {
                atomicAdd(&g_sum[m], s);
                atomicAdd(&g_sqsum[m], sq);
            }
        }
    }
}

// ---------------- BN normalize ----------------
__global__ void bn_kernel(float* __restrict__ out,
                          const float* __restrict__ gamma,
                          const float* __restrict__ beta)
{
    const long total4 = (long)Bn * COUTc * Hdim * Wdim / 4;
    long i4 = (long)blockIdx.x * blockDim.x + threadIdx.x;
    if (i4 >= total4) return;
    int c = (int)(i4 >> 10) & (COUTc - 1);
    const float invN = 1.0f / (float)(Bn * Hdim * Wdim);
    float mean  = g_sum[c] * invN;
    float var   = g_sqsum[c] * invN - mean * mean;
    float scale = gamma[c] * rsqrtf(var + 1e-5f);
    float shift = beta[c] - mean * scale;
    float4 v = reinterpret_cast<float4*>(out)[i4];
    v.x = v.x * scale + shift;
    v.y = v.y * scale + shift;
    v.z = v.z * scale + shift;
    v.w = v.w * scale + shift;
    reinterpret_cast<float4*>(out)[i4] = v;
}

// ---------------- launch ----------------
extern "C" void kernel_launch(void* const* d_in, const int* in_sizes, int n_in,
                              void* d_out, int out_size)
{
    const float* x     = (const float*)d_in[0];
    const float* w     = (const float*)d_in[1];
    const float* gamma = (const float*)d_in[2];
    const float* beta  = (const float*)d_in[3];
    float* out = (float*)d_out;

    cudaFuncSetAttribute(gemm_kernel, cudaFuncAttributeMaxDynamicSharedMemorySize,
                         SMEM_TOTAL);

    prep_w_kernel<<<70400, 256>>>(w);
    prep_x_kernel<<<65280, 256>>>(x);
    zero_stats_kernel<<<1, 256>>>();

    dim3 grid(2, 256);                 // 512 CTAs of 128 threads, 2 per SM
    gemm_kernel<<<grid, 128, SMEM_TOTAL>>>(out);

    const long total4 = (long)Bn * COUTc * Hdim * Wdim / 4;
    bn_kernel<<<(unsigned)((total4 + 255) / 256), 256>>>(out, gamma, beta);
}

// round 13
// speedup vs baseline: 10.7121x; 1.1503x over previous
#include <cuda_runtime.h>
#include <cuda_fp16.h>
#include <stdint.h>

// ---------------- problem constants ----------------
#define Bn    8
#define CINc  256
#define COUTc 256
#define Hdim  64
#define Wdim  64
#define HP    120
#define WP    68
#define NTAP  275
#define KQSTEPS 275    // 1100 total steps / 4 K-quarters

// ---------------- smem ----------------
#define OFF_B        16384
#define STAGE_STRIDE 32768          // A 16KB + B 16KB
#define SMEM_TOTAL   (STAGE_STRIDE * 3)    // 96KB -> 2 CTAs/SM

// ---------------- device scratch ----------------
__device__ __align__(256) __half g_xq[(size_t)Bn * HP * WP * CINc];
__device__ __align__(256) __half g_wq[(size_t)NTAP * COUTc * CINc];
__device__ __align__(16) float g_p1[(size_t)Bn * COUTc * Hdim * Wdim];
__device__ __align__(16) float g_p2[(size_t)Bn * COUTc * Hdim * Wdim];
__device__ __align__(16) float g_p3[(size_t)Bn * COUTc * Hdim * Wdim];
__device__ float g_sum[COUTc];
__device__ float g_sqsum[COUTc];

// ---------------- PTX helpers ----------------
__device__ __forceinline__ uint32_t smem_u32(const void* p) {
    uint32_t a;
    asm("{ .reg .u64 t; cvta.to.shared.u64 t, %1; cvt.u32.u64 %0, t; }"
        : "=r"(a) : "l"(p));
    return a;
}
__device__ __forceinline__ void cp16(uint32_t dst, const void* src) {
    asm volatile("cp.async.cg.shared.global [%0], [%1], 16;"
                 :: "r"(dst), "l"(src) : "memory");
}
#define CP_COMMIT() asm volatile("cp.async.commit_group;" ::: "memory")
#define CP_WAIT(n)  asm volatile("cp.async.wait_group %0;" :: "n"(n) : "memory")

__device__ __forceinline__ void ldsm4(uint32_t& r0, uint32_t& r1,
                                      uint32_t& r2, uint32_t& r3, uint32_t a) {
    asm volatile("ldmatrix.sync.aligned.m8n8.x4.shared.b16 {%0,%1,%2,%3}, [%4];"
                 : "=r"(r0), "=r"(r1), "=r"(r2), "=r"(r3) : "r"(a));
}
__device__ __forceinline__ void mma16816(float& d0, float& d1, float& d2, float& d3,
                                         uint32_t a0, uint32_t a1, uint32_t a2, uint32_t a3,
                                         uint32_t b0, uint32_t b1) {
    asm volatile("mma.sync.aligned.m16n8k16.row.col.f32.f16.f16.f32 "
                 "{%0,%1,%2,%3},{%4,%5,%6,%7},{%8,%9},{%0,%1,%2,%3};"
                 : "+f"(d0), "+f"(d1), "+f"(d2), "+f"(d3)
                 : "r"(a0), "r"(a1), "r"(a2), "r"(a3), "r"(b0), "r"(b1));
}

// ---------------- prep kernels ----------------
__global__ void prep_w_kernel(const float* __restrict__ w) {
    int idx = blockIdx.x * 256 + threadIdx.x;
    int ci  = idx & 255;
    int co  = (idx >> 8) & 255;
    int tap = idx >> 16;
    int t = tap / 5, kw = tap - 5 * t;
    int ik = t / 5,  kh = t - 5 * ik;
    g_wq[idx] = __float2half(
        w[(((size_t)(co * 11 + ik) * 256 + ci) * 25) + kh * 5 + kw]);
}

__global__ void prep_x_kernel(const float* __restrict__ x) {
    int idx = blockIdx.x * 256 + threadIdx.x;
    int ci   = idx & 255;
    int rest = idx >> 8;
    int wp = rest % WP;
    int r2 = rest / WP;
    int hp = r2 % HP;
    int b  = r2 / HP;
    int h = hp - 25, wq = wp - 2;
    float v = 0.f;
    if ((unsigned)h < 64u && (unsigned)wq < 64u)
        v = x[(((size_t)(b * 256 + ci) * 64) + h) * 64 + wq];
    g_xq[idx] = __float2half(v);
}

__global__ void zero_stats_kernel() {
    int t = threadIdx.x;
    if (t < COUTc) { g_sum[t] = 0.f; g_sqsum[t] = 0.f; }
}

// ---- fragment load / mma macros ----
#define LDFRAGS(BF, AH, KH, SO) do {                                               \
    _Pragma("unroll")                                                              \
    for (int ni = 0; ni < 4; ++ni)                                                 \
        ldsm4(BF[ni][0], BF[ni][1], BF[ni][2], BF[ni][3],                          \
              bB[KH] + (SO) + ni * 2048);                                          \
    _Pragma("unroll")                                                              \
    for (int mi = 0; mi < 4; ++mi)                                                 \
        ldsm4(AH[mi][0], AH[mi][1], AH[mi][2], AH[mi][3],                          \
              aB[KH] + (SO) + mi * 2048);                                          \
} while (0)

#define MMAS(BF, AH) do {                                                          \
    _Pragma("unroll")                                                              \
    for (int mi = 0; mi < 4; ++mi)                                                 \
        _Pragma("unroll")                                                          \
        for (int ni = 0; ni < 4; ++ni) {                                           \
            mma16816(acc[mi][2*ni][0], acc[mi][2*ni][1],                           \
                     acc[mi][2*ni][2], acc[mi][2*ni][3],                           \
                     AH[mi][0], AH[mi][1], AH[mi][2], AH[mi][3],                   \
                     BF[ni][0], BF[ni][2]);                                        \
            mma16816(acc[mi][2*ni+1][0], acc[mi][2*ni+1][1],                       \
                     acc[mi][2*ni+1][2], acc[mi][2*ni+1][3],                       \
                     AH[mi][0], AH[mi][1], AH[mi][2], AH[mi][3],                   \
                     BF[ni][1], BF[ni][3]);                                        \
        }                                                                          \
} while (0)

#define STEP(SO, ISSUE_STMT) do {                                                  \
    LDFRAGS(bf0, ah0, 0, SO);                                                      \
    ISSUE_STMT;                                                                    \
    LDFRAGS(bf1, ah1, 1, SO);                                                      \
    MMAS(bf0, ah0);                                                                \
    LDFRAGS(bf0, ah0, 2, SO);                                                      \
    MMAS(bf1, ah1);                                                                \
    LDFRAGS(bf1, ah1, 3, SO);                                                      \
    MMAS(bf0, ah0);                                                                \
    MMAS(bf1, ah1);                                                                \
} while (0)

// ---------------- main GEMM kernel (128 thr, K-quarter per CTA) ----------------
__global__ __launch_bounds__(128, 2)
void gemm_kernel(float* __restrict__ out)
{
    extern __shared__ __align__(1024) char smem[];
    const uint32_t sb = smem_u32(smem);

    const int tid  = threadIdx.x;
    const int w    = tid >> 5;               // 4 warps: 2m x 2n
    const int l    = tid & 31;
    const int mbase = blockIdx.x * 128;
    const int nblk  = blockIdx.y;
    const int kq    = blockIdx.z;            // K-quarter 0..3
    const int b     = nblk >> 5;
    const int i0    = (nblk & 31) * 2;

    // per-quarter start: global step s0
    const int s0   = KQSTEPS * kq;
    const int tap0 = s0 >> 2;
    const int kc0  = s0 & 3;
    const int t0   = s0 / 20;
    const int r0   = s0 % 20;

    // ---- copy geometry ----
    const int cA  = tid & 7;
    const int rA0 = tid >> 3;                // 0..15; rows rA0 + 16k
    const uint32_t swc = 16u * (uint32_t)(cA ^ (rA0 & 7));
    const uint32_t adst = sb + (uint32_t)rA0 * 128 + swc;

    const __half* aptr = g_wq + (size_t)tap0 * 65536
                       + (size_t)(mbase + rA0) * 256 + (size_t)cA * 8
                       + (size_t)kc0 * 64;
    const __half* xptr = g_xq + (size_t)b * (HP * WP * 256)
                       + ((size_t)i0 * WP + rA0) * 256 + (size_t)cA * 8
                       + (size_t)t0 * 17408 + (size_t)r0 * 64;
    int ac4  = kc0;
    int xc20 = r0;

    // ---- mma geometry: warp tile 64x64 ----
    const int mrow0 = (w >> 1) * 64;
    const int nrow0 = (w & 1) * 64;
    const uint32_t swz = (uint32_t)(l & 7);
    const uint32_t hl  = (uint32_t)(l >> 4);
    const uint32_t aLaneOff = (uint32_t)(mrow0 + (l & 15)) * 128;
    const uint32_t bLaneOff = (uint32_t)(nrow0 + (l & 7) + ((l >> 3) & 1) * 8) * 128;

    uint32_t aB[4], bB[4];
#pragma unroll
    for (int kh = 0; kh < 4; ++kh) {
        const uint32_t ch = 2u * kh + hl;
        aB[kh] = sb + aLaneOff + 16u * (ch ^ swz);
        bB[kh] = sb + OFF_B + bLaneOff + 16u * (ch ^ swz);
    }

    float acc[4][8][4];
#pragma unroll
    for (int mi = 0; mi < 4; ++mi)
#pragma unroll
        for (int nj = 0; nj < 8; ++nj)
#pragma unroll
            for (int r = 0; r < 4; ++r) acc[mi][nj][r] = 0.f;

    uint32_t bf0[4][4], bf1[4][4], ah0[4][4], ah1[4][4];

    auto issue = [&](const uint32_t so) {
#pragma unroll
        for (int k = 0; k < 8; ++k)
            cp16(so + adst + k * 2048, aptr + k * 4096);
#pragma unroll
        for (int k = 0; k < 8; ++k)
            cp16(so + adst + OFF_B + k * 2048,
                 xptr + (k >> 2) * 17408 + (k & 3) * 4096);
        aptr += (ac4 == 3) ? 65344 : 64;
        ac4 = (ac4 + 1) & 3;
        xptr += (xc20 == 19) ? 16192 : 64;
        xc20 = (xc20 == 19) ? 0 : xc20 + 1;
    };

    // prologue: local steps 0,1 -> stages 0,1
    issue(0);              CP_COMMIT();
    issue(STAGE_STRIDE);   CP_COMMIT();

    // main: 91 x 3 = 273 compute steps; tails 273,274 -> total 275
    for (int i = 0; i < 91; ++i) {
        CP_WAIT(1);
        __syncthreads();
        STEP(0,                { issue(2 * STAGE_STRIDE); CP_COMMIT(); });
        CP_WAIT(1);
        __syncthreads();
        STEP(STAGE_STRIDE,     { issue(0);                CP_COMMIT(); });
        CP_WAIT(1);
        __syncthreads();
        STEP(2 * STAGE_STRIDE, { issue(STAGE_STRIDE);     CP_COMMIT(); });
    }
    CP_WAIT(1);
    __syncthreads();
    STEP(0, (void)0);
    CP_WAIT(0);
    __syncthreads();
    STEP(STAGE_STRIDE, (void)0);

    // ---- epilogue: plain stores to per-quarter buffer (no stats) ----
    float* dst;
    if      (kq == 0) dst = out;
    else if (kq == 1) dst = g_p1;
    else if (kq == 2) dst = g_p2;
    else              dst = g_p3;

    const int lg = l >> 2;
    const int lc = l & 3;
    const int orow = i0 + (w & 1);

#pragma unroll
    for (int mi = 0; mi < 4; ++mi) {
#pragma unroll
        for (int h = 0; h < 2; ++h) {
            const int m = mbase + mrow0 + mi * 16 + lg + h * 8;
            float* rowp = dst + (((size_t)(b * 256 + m)) * 64 + orow) * 64 + 2 * lc;
#pragma unroll
            for (int nj = 0; nj < 8; ++nj)
                reinterpret_cast<float2*>(rowp + nj * 8)[0] =
                    make_float2(acc[mi][nj][2 * h], acc[mi][nj][2 * h + 1]);
        }
    }
}

// ---------------- reduce partials + BN stats ----------------
// One block per (b, c): 4096 floats = 1024 float4; 256 threads x 4 float4.
__global__ void reduce_stats_kernel(float* __restrict__ out)
{
    __shared__ float ssum[8], ssq[8];
    const int blk = blockIdx.x;              // b*256 + c
    const int c   = blk & 255;
    const int tid = threadIdx.x;
    const size_t base4 = (size_t)blk * 1024;

    float4* o4 = reinterpret_cast<float4*>(out);
    const float4* p1 = reinterpret_cast<const float4*>(g_p1);
    const float4* p2 = reinterpret_cast<const float4*>(g_p2);
    const float4* p3 = reinterpret_cast<const float4*>(g_p3);

    float s = 0.f, sq = 0.f;
#pragma unroll
    for (int k = 0; k < 4; ++k) {
        const size_t i4 = base4 + tid + k * 256;
        float4 a = o4[i4], q1 = p1[i4], q2 = p2[i4], q3 = p3[i4];
        float4 v;
        v.x = a.x + q1.x + q2.x + q3.x;
        v.y = a.y + q1.y + q2.y + q3.y;
        v.z = a.z + q1.z + q2.z + q3.z;
        v.w = a.w + q1.w + q2.w + q3.w;
        o4[i4] = v;
        s  += v.x + v.y + v.z + v.w;
        sq += v.x * v.x + v.y * v.y + v.z * v.z + v.w * v.w;
    }
#pragma unroll
    for (int o = 16; o > 0; o >>= 1) {
        s  += __shfl_xor_sync(0xffffffffu, s,  o);
        sq += __shfl_xor_sync(0xffffffffu, sq, o);
    }
    if ((tid & 31) == 0) { ssum[tid >> 5] = s; ssq[tid >> 5] = sq; }
    __syncthreads();
    if (tid == 0) {
        float ts = 0.f, tq = 0.f;
#pragma unroll
        for (int k = 0; k < 8; ++k) { ts += ssum[k]; tq += ssq[k]; }
        atomicAdd(&g_sum[c], ts);
        atomicAdd(&g_sqsum[c], tq);
    }
}

// ---------------- BN normalize ----------------
__global__ void bn_kernel(float* __restrict__ out,
                          const float* __restrict__ gamma,
                          const float* __restrict__ beta)
{
    const long total4 = (long)Bn * COUTc * Hdim * Wdim / 4;
    long i4 = (long)blockIdx.x * blockDim.x + threadIdx.x;
    if (i4 >= total4) return;
    int c = (int)(i4 >> 10) & (COUTc - 1);
    const float invN = 1.0f / (float)(Bn * Hdim * Wdim);
    float mean  = g_sum[c] * invN;
    float var   = g_sqsum[c] * invN - mean * mean;
    float scale = gamma[c] * rsqrtf(var + 1e-5f);
    float shift = beta[c] - mean * scale;
    float4 v = reinterpret_cast<float4*>(out)[i4];
    v.x = v.x * scale + shift;
    v.y = v.y * scale + shift;
    v.z = v.z * scale + shift;
    v.w = v.w * scale + shift;
    reinterpret_cast<float4*>(out)[i4] = v;
}

// ---------------- launch ----------------
extern "C" void kernel_launch(void* const* d_in, const int* in_sizes, int n_in,
                              void* d_out, int out_size)
{
    const float* x     = (const float*)d_in[0];
    const float* w     = (const float*)d_in[1];
    const float* gamma = (const float*)d_in[2];
    const float* beta  = (const float*)d_in[3];
    float* out = (float*)d_out;

    cudaFuncSetAttribute(gemm_kernel, cudaFuncAttributeMaxDynamicSharedMemorySize,
                         SMEM_TOTAL);

    prep_w_kernel<<<70400, 256>>>(w);
    prep_x_kernel<<<65280, 256>>>(x);
    zero_stats_kernel<<<1, 256>>>();

    dim3 grid(2, 256, 4);              // 2048 CTAs: (mhalf, nblk, kquarter)
    gemm_kernel<<<grid, 128, SMEM_TOTAL>>>(out);

    reduce_stats_kernel<<<Bn * COUTc, 256>>>(out);   // 2048 blocks

    const long total4 = (long)Bn * COUTc * Hdim * Wdim / 4;
    bn_kernel<<<(unsigned)((total4 + 255) / 256), 256>>>(out, gamma, beta);
}

// round 14
// speedup vs baseline: 10.7618x; 1.0046x over previous
#include <cuda_runtime.h>
#include <cuda_fp16.h>
#include <stdint.h>

// ---------------- problem constants ----------------
#define Bn    8
#define CINc  256
#define COUTc 256
#define Hdim  64
#define Wdim  64
#define HP    120
#define WP    68
#define NTAP  275
#define KQSTEPS 275    // 1100 total steps / 4 K-quarters

// ---------------- smem ----------------
#define OFF_B        16384
#define STAGE_STRIDE 32768          // A 16KB + B 16KB
#define MB_OFF       98304          // 6 mbarriers (8B each)
#define SMEM_TOTAL   (MB_OFF + 64)  // ~96KB -> 2 CTAs/SM

// ---------------- device scratch ----------------
__device__ __align__(256) __half g_xq[(size_t)Bn * HP * WP * CINc];
__device__ __align__(256) __half g_wq[(size_t)NTAP * COUTc * CINc];
__device__ __align__(16) float g_p1[(size_t)Bn * COUTc * Hdim * Wdim];
__device__ __align__(16) float g_p2[(size_t)Bn * COUTc * Hdim * Wdim];
__device__ __align__(16) float g_p3[(size_t)Bn * COUTc * Hdim * Wdim];
__device__ float g_sum[COUTc];
__device__ float g_sqsum[COUTc];

// ---------------- PTX helpers ----------------
__device__ __forceinline__ uint32_t smem_u32(const void* p) {
    uint32_t a;
    asm("{ .reg .u64 t; cvta.to.shared.u64 t, %1; cvt.u32.u64 %0, t; }"
        : "=r"(a) : "l"(p));
    return a;
}
__device__ __forceinline__ void cp16(uint32_t dst, const void* src) {
    asm volatile("cp.async.cg.shared.global [%0], [%1], 16;"
                 :: "r"(dst), "l"(src) : "memory");
}

// mbarrier ops (sm_80/90 generic)
#define MBINIT(addr) \
    asm volatile("mbarrier.init.shared.b64 [%0], 128;" :: "r"(addr) : "memory")
#define MBARRIVE(addr) \
    asm volatile("{ .reg .b64 t; mbarrier.arrive.shared.b64 t, [%0]; }" \
                 :: "r"(addr) : "memory")
#define CPARRIVE(addr) \
    asm volatile("cp.async.mbarrier.arrive.noinc.shared.b64 [%0];" \
                 :: "r"(addr) : "memory")
#define MWAIT(addr, par) do {                                                       \
    uint32_t _mb = (addr); uint32_t _pa = (par); uint32_t _done;                    \
    asm volatile("{ .reg .pred p;"                                                  \
        " mbarrier.try_wait.parity.acquire.cta.shared::cta.b64 p, [%1], %2;"        \
        " selp.b32 %0,1,0,p; }" : "=r"(_done) : "r"(_mb), "r"(_pa) : "memory");     \
    if (!_done) {                                                                    \
        asm volatile("{ .reg .pred P1;"                                             \
            " WL_%=:"                                                               \
            " mbarrier.try_wait.parity.acquire.cta.shared::cta.b64 P1, [%0], %1, 0x989680;" \
            " @P1 bra.uni WD_%=;"                                                   \
            " bra.uni WL_%=;"                                                       \
            " WD_%=: }" :: "r"(_mb), "r"(_pa) : "memory");                          \
    }                                                                                \
} while (0)

__device__ __forceinline__ void ldsm4(uint32_t& r0, uint32_t& r1,
                                      uint32_t& r2, uint32_t& r3, uint32_t a) {
    asm volatile("ldmatrix.sync.aligned.m8n8.x4.shared.b16 {%0,%1,%2,%3}, [%4];"
                 : "=r"(r0), "=r"(r1), "=r"(r2), "=r"(r3) : "r"(a));
}
__device__ __forceinline__ void mma16816(float& d0, float& d1, float& d2, float& d3,
                                         uint32_t a0, uint32_t a1, uint32_t a2, uint32_t a3,
                                         uint32_t b0, uint32_t b1) {
    asm volatile("mma.sync.aligned.m16n8k16.row.col.f32.f16.f16.f32 "
                 "{%0,%1,%2,%3},{%4,%5,%6,%7},{%8,%9},{%0,%1,%2,%3};"
                 : "+f"(d0), "+f"(d1), "+f"(d2), "+f"(d3)
                 : "r"(a0), "r"(a1), "r"(a2), "r"(a3), "r"(b0), "r"(b1));
}

// ---------------- prep kernels ----------------
__global__ void prep_w_kernel(const float* __restrict__ w) {
    int idx = blockIdx.x * 256 + threadIdx.x;
    int ci  = idx & 255;
    int co  = (idx >> 8) & 255;
    int tap = idx >> 16;
    int t = tap / 5, kw = tap - 5 * t;
    int ik = t / 5,  kh = t - 5 * ik;
    g_wq[idx] = __float2half(
        w[(((size_t)(co * 11 + ik) * 256 + ci) * 25) + kh * 5 + kw]);
}

__global__ void prep_x_kernel(const float* __restrict__ x) {
    int idx = blockIdx.x * 256 + threadIdx.x;
    int ci   = idx & 255;
    int rest = idx >> 8;
    int wp = rest % WP;
    int r2 = rest / WP;
    int hp = r2 % HP;
    int b  = r2 / HP;
    int h = hp - 25, wq = wp - 2;
    float v = 0.f;
    if ((unsigned)h < 64u && (unsigned)wq < 64u)
        v = x[(((size_t)(b * 256 + ci) * 64) + h) * 64 + wq];
    g_xq[idx] = __float2half(v);
}

__global__ void zero_stats_kernel() {
    int t = threadIdx.x;
    if (t < COUTc) { g_sum[t] = 0.f; g_sqsum[t] = 0.f; }
}

// ---- fragment load / mma macros ----
#define LDFRAGS(BF, AH, KH, SO) do {                                               \
    _Pragma("unroll")                                                              \
    for (int ni = 0; ni < 4; ++ni)                                                 \
        ldsm4(BF[ni][0], BF[ni][1], BF[ni][2], BF[ni][3],                          \
              bB[KH] + (SO) + ni * 2048);                                          \
    _Pragma("unroll")                                                              \
    for (int mi = 0; mi < 4; ++mi)                                                 \
        ldsm4(AH[mi][0], AH[mi][1], AH[mi][2], AH[mi][3],                          \
              aB[KH] + (SO) + mi * 2048);                                          \
} while (0)

#define MMAS(BF, AH) do {                                                          \
    _Pragma("unroll")                                                              \
    for (int mi = 0; mi < 4; ++mi)                                                 \
        _Pragma("unroll")                                                          \
        for (int ni = 0; ni < 4; ++ni) {                                           \
            mma16816(acc[mi][2*ni][0], acc[mi][2*ni][1],                           \
                     acc[mi][2*ni][2], acc[mi][2*ni][3],                           \
                     AH[mi][0], AH[mi][1], AH[mi][2], AH[mi][3],                   \
                     BF[ni][0], BF[ni][2]);                                        \
            mma16816(acc[mi][2*ni+1][0], acc[mi][2*ni+1][1],                       \
                     acc[mi][2*ni+1][2], acc[mi][2*ni+1][3],                       \
                     AH[mi][0], AH[mi][1], AH[mi][2], AH[mi][3],                   \
                     BF[ni][1], BF[ni][3]);                                        \
        }                                                                          \
} while (0)

// Full pipelined step: consume stage RJ, fill stage FJ=(RJ+2)%3, parity P.
#define STEP_FULL(SO, RJ, FJ, P) do {                                              \
    MWAIT(mbR[RJ], P);                                                             \
    LDFRAGS(bf0, ah0, 0, SO);                                                      \
    MWAIT(mbF[FJ], P);                                                             \
    issue((FJ) * STAGE_STRIDE);                                                    \
    CPARRIVE(mbR[FJ]);                                                             \
    LDFRAGS(bf1, ah1, 1, SO);                                                      \
    MMAS(bf0, ah0);                                                                \
    LDFRAGS(bf0, ah0, 2, SO);                                                      \
    MMAS(bf1, ah1);                                                                \
    LDFRAGS(bf1, ah1, 3, SO);                                                      \
    MBARRIVE(mbF[RJ]);                                                             \
    MMAS(bf0, ah0);                                                                \
    MMAS(bf1, ah1);                                                                \
} while (0)

// Tail step: consume only.
#define STEP_TAIL(SO, RJ, P) do {                                                  \
    MWAIT(mbR[RJ], P);                                                             \
    LDFRAGS(bf0, ah0, 0, SO);                                                      \
    LDFRAGS(bf1, ah1, 1, SO);                                                      \
    MMAS(bf0, ah0);                                                                \
    LDFRAGS(bf0, ah0, 2, SO);                                                      \
    MMAS(bf1, ah1);                                                                \
    LDFRAGS(bf1, ah1, 3, SO);                                                      \
    MMAS(bf0, ah0);                                                                \
    MMAS(bf1, ah1);                                                                \
} while (0)

// ---------------- main GEMM kernel (128 thr, K-quarter per CTA) ----------------
__global__ __launch_bounds__(128, 2)
void gemm_kernel(float* __restrict__ out)
{
    extern __shared__ __align__(1024) char smem[];
    const uint32_t sb = smem_u32(smem);

    const int tid  = threadIdx.x;
    const int w    = tid >> 5;               // 4 warps: 2m x 2n
    const int l    = tid & 31;
    const int mbase = blockIdx.x * 128;
    const int nblk  = blockIdx.y;
    const int kq    = blockIdx.z;            // K-quarter 0..3
    const int b     = nblk >> 5;
    const int i0    = (nblk & 31) * 2;

    // mbarriers: READY[3], FREE[3]
    uint32_t mbR[3], mbF[3];
#pragma unroll
    for (int j = 0; j < 3; ++j) {
        mbR[j] = sb + MB_OFF + 8 * j;
        mbF[j] = sb + MB_OFF + 24 + 8 * j;
    }
    if (tid == 0) {
#pragma unroll
        for (int j = 0; j < 3; ++j) { MBINIT(mbR[j]); MBINIT(mbF[j]); }
    }
    __syncthreads();

    // per-quarter start: global step s0
    const int s0   = KQSTEPS * kq;
    const int tap0 = s0 >> 2;
    const int kc0  = s0 & 3;
    const int t0   = s0 / 20;
    const int r0   = s0 % 20;

    // ---- copy geometry ----
    const int cA  = tid & 7;
    const int rA0 = tid >> 3;                // 0..15; rows rA0 + 16k
    const uint32_t swc = 16u * (uint32_t)(cA ^ (rA0 & 7));
    const uint32_t adst = sb + (uint32_t)rA0 * 128 + swc;

    const __half* aptr = g_wq + (size_t)tap0 * 65536
                       + (size_t)(mbase + rA0) * 256 + (size_t)cA * 8
                       + (size_t)kc0 * 64;
    const __half* xptr = g_xq + (size_t)b * (HP * WP * 256)
                       + ((size_t)i0 * WP + rA0) * 256 + (size_t)cA * 8
                       + (size_t)t0 * 17408 + (size_t)r0 * 64;
    int ac4  = kc0;
    int xc20 = r0;

    // ---- mma geometry: warp tile 64x64 ----
    const int mrow0 = (w >> 1) * 64;
    const int nrow0 = (w & 1) * 64;
    const uint32_t swz = (uint32_t)(l & 7);
    const uint32_t hl  = (uint32_t)(l >> 4);
    const uint32_t aLaneOff = (uint32_t)(mrow0 + (l & 15)) * 128;
    const uint32_t bLaneOff = (uint32_t)(nrow0 + (l & 7) + ((l >> 3) & 1) * 8) * 128;

    uint32_t aB[4], bB[4];
#pragma unroll
    for (int kh = 0; kh < 4; ++kh) {
        const uint32_t ch = 2u * kh + hl;
        aB[kh] = sb + aLaneOff + 16u * (ch ^ swz);
        bB[kh] = sb + OFF_B + bLaneOff + 16u * (ch ^ swz);
    }

    float acc[4][8][4];
#pragma unroll
    for (int mi = 0; mi < 4; ++mi)
#pragma unroll
        for (int nj = 0; nj < 8; ++nj)
#pragma unroll
            for (int r = 0; r < 4; ++r) acc[mi][nj][r] = 0.f;

    uint32_t bf0[4][4], bf1[4][4], ah0[4][4], ah1[4][4];

    auto issue = [&](const uint32_t so) {
#pragma unroll
        for (int k = 0; k < 8; ++k)
            cp16(so + adst + k * 2048, aptr + k * 4096);
#pragma unroll
        for (int k = 0; k < 8; ++k)
            cp16(so + adst + OFF_B + k * 2048,
                 xptr + (k >> 2) * 17408 + (k & 3) * 4096);
        aptr += (ac4 == 3) ? 65344 : 64;
        ac4 = (ac4 + 1) & 3;
        xptr += (xc20 == 19) ? 16192 : 64;
        xc20 = (xc20 == 19) ? 0 : xc20 + 1;
    };

    // prologue: fill stages 0,1; pre-free stage 2
    issue(0);              CPARRIVE(mbR[0]);
    issue(STAGE_STRIDE);   CPARRIVE(mbR[1]);
    MBARRIVE(mbF[2]);

    // main: 91 macro-iters x 3 steps = 273; parity = i&1 for every wait
    for (int i = 0; i < 91; ++i) {
        const uint32_t p = (uint32_t)(i & 1);
        STEP_FULL(0,                0, 2, p);   // s=3i
        STEP_FULL(STAGE_STRIDE,     1, 0, p);   // s=3i+1
        STEP_FULL(2 * STAGE_STRIDE, 2, 1, p);   // s=3i+2
    }
    // tails: s=273 (stage 0), s=274 (stage 1); use index 91 -> parity 1
    STEP_TAIL(0,            0, 1u);
    STEP_TAIL(STAGE_STRIDE, 1, 1u);

    // ---- epilogue: plain stores to per-quarter buffer ----
    float* dst;
    if      (kq == 0) dst = out;
    else if (kq == 1) dst = g_p1;
    else if (kq == 2) dst = g_p2;
    else              dst = g_p3;

    const int lg = l >> 2;
    const int lc = l & 3;
    const int orow = i0 + (w & 1);

#pragma unroll
    for (int mi = 0; mi < 4; ++mi) {
#pragma unroll
        for (int h = 0; h < 2; ++h) {
            const int m = mbase + mrow0 + mi * 16 + lg + h * 8;
            float* rowp = dst + (((size_t)(b * 256 + m)) * 64 + orow) * 64 + 2 * lc;
#pragma unroll
            for (int nj = 0; nj < 8; ++nj)
                reinterpret_cast<float2*>(rowp + nj * 8)[0] =
                    make_float2(acc[mi][nj][2 * h], acc[mi][nj][2 * h + 1]);
        }
    }
}

// ---------------- reduce partials + BN stats ----------------
__global__ void reduce_stats_kernel(float* __restrict__ out)
{
    __shared__ float ssum[8], ssq[8];
    const int blk = blockIdx.x;              // b*256 + c
    const int c   = blk & 255;
    const int tid = threadIdx.x;
    const size_t base4 = (size_t)blk * 1024;

    float4* o4 = reinterpret_cast<float4*>(out);
    const float4* p1 = reinterpret_cast<const float4*>(g_p1);
    const float4* p2 = reinterpret_cast<const float4*>(g_p2);
    const float4* p3 = reinterpret_cast<const float4*>(g_p3);

    float s = 0.f, sq = 0.f;
#pragma unroll
    for (int k = 0; k < 4; ++k) {
        const size_t i4 = base4 + tid + k * 256;
        float4 a = o4[i4], q1 = p1[i4], q2 = p2[i4], q3 = p3[i4];
        float4 v;
        v.x = a.x + q1.x + q2.x + q3.x;
        v.y = a.y + q1.y + q2.y + q3.y;
        v.z = a.z + q1.z + q2.z + q3.z;
        v.w = a.w + q1.w + q2.w + q3.w;
        o4[i4] = v;
        s  += v.x + v.y + v.z + v.w;
        sq += v.x * v.x + v.y * v.y + v.z * v.z + v.w * v.w;
    }
#pragma unroll
    for (int o = 16; o > 0; o >>= 1) {
        s  += __shfl_xor_sync(0xffffffffu, s,  o);
        sq += __shfl_xor_sync(0xffffffffu, sq, o);
    }
    if ((tid & 31) == 0) { ssum[tid >> 5] = s; ssq[tid >> 5] = sq; }
    __syncthreads();
    if (tid == 0) {
        float ts = 0.f, tq = 0.f;
#pragma unroll
        for (int k = 0; k < 8; ++k) { ts += ssum[k]; tq += ssq[k]; }
        atomicAdd(&g_sum[c], ts);
        atomicAdd(&g_sqsum[c], tq);
    }
}

// ---------------- BN normalize ----------------
__global__ void bn_kernel(float* __restrict__ out,
                          const float* __restrict__ gamma,
                          const float* __restrict__ beta)
{
    const long total4 = (long)Bn * COUTc * Hdim * Wdim / 4;
    long i4 = (long)blockIdx.x * blockDim.x + threadIdx.x;
    if (i4 >= total4) return;
    int c = (int)(i4 >> 10) & (COUTc - 1);
    const float invN = 1.0f / (float)(Bn * Hdim * Wdim);
    float mean  = g_sum[c] * invN;
    float var   = g_sqsum[c] * invN - mean * mean;
    float scale = gamma[c] * rsqrtf(var + 1e-5f);
    float shift = beta[c] - mean * scale;
    float4 v = reinterpret_cast<float4*>(out)[i4];
    v.x = v.x * scale + shift;
    v.y = v.y * scale + shift;
    v.z = v.z * scale + shift;
    v.w = v.w * scale + shift;
    reinterpret_cast<float4*>(out)[i4] = v;
}

// ---------------- launch ----------------
extern "C" void kernel_launch(void* const* d_in, const int* in_sizes, int n_in,
                              void* d_out, int out_size)
{
    const float* x     = (const float*)d_in[0];
    const float* w     = (const float*)d_in[1];
    const float* gamma = (const float*)d_in[2];
    const float* beta  = (const float*)d_in[3];
    float* out = (float*)d_out;

    cudaFuncSetAttribute(gemm_kernel, cudaFuncAttributeMaxDynamicSharedMemorySize,
                         SMEM_TOTAL);

    prep_w_kernel<<<70400, 256>>>(w);
    prep_x_kernel<<<65280, 256>>>(x);
    zero_stats_kernel<<<1, 256>>>();

    dim3 grid(2, 256, 4);              // 2048 CTAs: (mhalf, nblk, kquarter)
    gemm_kernel<<<grid, 128, SMEM_TOTAL>>>(out);

    reduce_stats_kernel<<<Bn * COUTc, 256>>>(out);   // 2048 blocks

    const long total4 = (long)Bn * COUTc * Hdim * Wdim / 4;
    bn_kernel<<<(unsigned)((total4 + 255) / 256), 256>>>(out, gamma, beta);
}

// round 15
// speedup vs baseline: 10.9958x; 1.0217x over previous
#include <cuda_runtime.h>
#include <cuda_fp16.h>
#include <stdint.h>

// ---------------- problem constants ----------------
#define Bn    8
#define CINc  256
#define COUTc 256
#define Hdim  64
#define Wdim  64
#define HP    120
#define WP    68
#define NTAP  275
#define KQSTEPS 275    // 1100 total steps / 4 K-quarters

// ---------------- smem (gemm) ----------------
#define OFF_B        16384
#define STAGE_STRIDE 32768          // A 16KB + B 16KB
#define MB_OFF       98304          // 6 mbarriers (8B each)
#define SMEM_TOTAL   (MB_OFF + 64)  // ~96KB -> 2 CTAs/SM

// ---------------- device scratch ----------------
__device__ __align__(256) __half g_xq[(size_t)Bn * HP * WP * CINc];
__device__ __align__(256) __half g_wq[(size_t)NTAP * COUTc * CINc];
__device__ __align__(16) float g_p1[(size_t)Bn * COUTc * Hdim * Wdim];
__device__ __align__(16) float g_p2[(size_t)Bn * COUTc * Hdim * Wdim];
__device__ __align__(16) float g_p3[(size_t)Bn * COUTc * Hdim * Wdim];

// ---------------- PTX helpers ----------------
__device__ __forceinline__ uint32_t smem_u32(const void* p) {
    uint32_t a;
    asm("{ .reg .u64 t; cvta.to.shared.u64 t, %1; cvt.u32.u64 %0, t; }"
        : "=r"(a) : "l"(p));
    return a;
}
__device__ __forceinline__ void cp16(uint32_t dst, const void* src) {
    asm volatile("cp.async.cg.shared.global [%0], [%1], 16;"
                 :: "r"(dst), "l"(src) : "memory");
}

// mbarrier ops (sm_80/90 generic)
#define MBINIT(addr) \
    asm volatile("mbarrier.init.shared.b64 [%0], 128;" :: "r"(addr) : "memory")
#define MBARRIVE(addr) \
    asm volatile("{ .reg .b64 t; mbarrier.arrive.shared.b64 t, [%0]; }" \
                 :: "r"(addr) : "memory")
#define CPARRIVE(addr) \
    asm volatile("cp.async.mbarrier.arrive.noinc.shared.b64 [%0];" \
                 :: "r"(addr) : "memory")
#define MWAIT(addr, par) do {                                                       \
    uint32_t _mb = (addr); uint32_t _pa = (par); uint32_t _done;                    \
    asm volatile("{ .reg .pred p;"                                                  \
        " mbarrier.try_wait.parity.acquire.cta.shared::cta.b64 p, [%1], %2;"        \
        " selp.b32 %0,1,0,p; }" : "=r"(_done) : "r"(_mb), "r"(_pa) : "memory");     \
    if (!_done) {                                                                    \
        asm volatile("{ .reg .pred P1;"                                             \
            " WL_%=:"                                                               \
            " mbarrier.try_wait.parity.acquire.cta.shared::cta.b64 P1, [%0], %1, 0x989680;" \
            " @P1 bra.uni WD_%=;"                                                   \
            " bra.uni WL_%=;"                                                       \
            " WD_%=: }" :: "r"(_mb), "r"(_pa) : "memory");                          \
    }                                                                                \
} while (0)

__device__ __forceinline__ void ldsm4(uint32_t& r0, uint32_t& r1,
                                      uint32_t& r2, uint32_t& r3, uint32_t a) {
    asm volatile("ldmatrix.sync.aligned.m8n8.x4.shared.b16 {%0,%1,%2,%3}, [%4];"
                 : "=r"(r0), "=r"(r1), "=r"(r2), "=r"(r3) : "r"(a));
}
__device__ __forceinline__ void mma16816(float& d0, float& d1, float& d2, float& d3,
                                         uint32_t a0, uint32_t a1, uint32_t a2, uint32_t a3,
                                         uint32_t b0, uint32_t b1) {
    asm volatile("mma.sync.aligned.m16n8k16.row.col.f32.f16.f16.f32 "
                 "{%0,%1,%2,%3},{%4,%5,%6,%7},{%8,%9},{%0,%1,%2,%3};"
                 : "+f"(d0), "+f"(d1), "+f"(d2), "+f"(d3)
                 : "r"(a0), "r"(a1), "r"(a2), "r"(a3), "r"(b0), "r"(b1));
}

// ---------------- prep kernels (coalesced smem-transpose versions) ----------------
// W: block per (co, ik); coalesced read of 256ci x 25taps, transpose, contiguous write.
__global__ __launch_bounds__(256)
void prep_w_kernel(const float* __restrict__ w) {
    __shared__ __half s[25][260];
    const int g  = blockIdx.x;        // co*11 + ik
    const int co = g / 11;
    const int ik = g - co * 11;
    const int tid = threadIdx.x;

    const float* src = w + (size_t)g * 6400;
#pragma unroll
    for (int e = tid; e < 6400; e += 256) {
        const int ci = e / 25;
        const int r  = e - ci * 25;
        s[r][ci] = __float2half(src[e]);
    }
    __syncthreads();

    __half* dstb = g_wq + (size_t)(ik * 25) * 65536 + (size_t)co * 256;
#pragma unroll
    for (int r = 0; r < 25; ++r)
        dstb[(size_t)r * 65536 + tid] = s[r][tid];   // tap = ik*25 + r
}

// X: block per (b, hp) plane; coalesced reads, transpose [w][ci] -> [wp][ci], pads zero.
__global__ __launch_bounds__(256)
void prep_x_kernel(const float* __restrict__ x) {
    __shared__ __half s[64][260];
    const int hp  = blockIdx.x;       // 0..119
    const int b   = blockIdx.y;       // 0..7
    const int tid = threadIdx.x;
    const int h   = hp - 25;

    __half* plane = g_xq + (size_t)(b * HP + hp) * (WP * 256);

    if ((unsigned)h >= 64u) {
        for (int j = tid; j < WP * 256; j += 256)
            plane[j] = __float2half(0.f);
        return;
    }

    const int wj  = tid & 63;
    const int cig = tid >> 6;         // 0..3
    const float* srcb = x + (size_t)b * (256 * 4096) + (size_t)h * 64;
#pragma unroll 4
    for (int cc = 0; cc < 64; ++cc) {
        const int ci = cc * 4 + cig;
        s[wj][ci] = __float2half(srcb[(size_t)ci * 4096 + wj]);
    }
    __syncthreads();

#pragma unroll 4
    for (int wp = 0; wp < WP; ++wp) {
        const int wq = wp - 2;
        __half v = ((unsigned)wq < 64u) ? s[wq][tid] : __float2half(0.f);
        plane[wp * 256 + tid] = v;
    }
}

// ---- fragment load / mma macros ----
#define LDFRAGS(BF, AH, KH, SO) do {                                               \
    _Pragma("unroll")                                                              \
    for (int ni = 0; ni < 4; ++ni)                                                 \
        ldsm4(BF[ni][0], BF[ni][1], BF[ni][2], BF[ni][3],                          \
              bB[KH] + (SO) + ni * 2048);                                          \
    _Pragma("unroll")                                                              \
    for (int mi = 0; mi < 4; ++mi)                                                 \
        ldsm4(AH[mi][0], AH[mi][1], AH[mi][2], AH[mi][3],                          \
              aB[KH] + (SO) + mi * 2048);                                          \
} while (0)

#define MMAS(BF, AH) do {                                                          \
    _Pragma("unroll")                                                              \
    for (int mi = 0; mi < 4; ++mi)                                                 \
        _Pragma("unroll")                                                          \
        for (int ni = 0; ni < 4; ++ni) {                                           \
            mma16816(acc[mi][2*ni][0], acc[mi][2*ni][1],                           \
                     acc[mi][2*ni][2], acc[mi][2*ni][3],                           \
                     AH[mi][0], AH[mi][1], AH[mi][2], AH[mi][3],                   \
                     BF[ni][0], BF[ni][2]);                                        \
            mma16816(acc[mi][2*ni+1][0], acc[mi][2*ni+1][1],                       \
                     acc[mi][2*ni+1][2], acc[mi][2*ni+1][3],                       \
                     AH[mi][0], AH[mi][1], AH[mi][2], AH[mi][3],                   \
                     BF[ni][1], BF[ni][3]);                                        \
        }                                                                          \
} while (0)

#define STEP_FULL(SO, RJ, FJ, P) do {                                              \
    MWAIT(mbR[RJ], P);                                                             \
    LDFRAGS(bf0, ah0, 0, SO);                                                      \
    MWAIT(mbF[FJ], P);                                                             \
    issue((FJ) * STAGE_STRIDE);                                                    \
    CPARRIVE(mbR[FJ]);                                                             \
    LDFRAGS(bf1, ah1, 1, SO);                                                      \
    MMAS(bf0, ah0);                                                                \
    LDFRAGS(bf0, ah0, 2, SO);                                                      \
    MMAS(bf1, ah1);                                                                \
    LDFRAGS(bf1, ah1, 3, SO);                                                      \
    MBARRIVE(mbF[RJ]);                                                             \
    MMAS(bf0, ah0);                                                                \
    MMAS(bf1, ah1);                                                                \
} while (0)

#define STEP_TAIL(SO, RJ, P) do {                                                  \
    MWAIT(mbR[RJ], P);                                                             \
    LDFRAGS(bf0, ah0, 0, SO);                                                      \
    LDFRAGS(bf1, ah1, 1, SO);                                                      \
    MMAS(bf0, ah0);                                                                \
    LDFRAGS(bf0, ah0, 2, SO);                                                      \
    MMAS(bf1, ah1);                                                                \
    LDFRAGS(bf1, ah1, 3, SO);                                                      \
    MMAS(bf0, ah0);                                                                \
    MMAS(bf1, ah1);                                                                \
} while (0)

// ---------------- main GEMM kernel (unchanged from R14) ----------------
__global__ __launch_bounds__(128, 2)
void gemm_kernel(float* __restrict__ out)
{
    extern __shared__ __align__(1024) char smem[];
    const uint32_t sb = smem_u32(smem);

    const int tid  = threadIdx.x;
    const int w    = tid >> 5;
    const int l    = tid & 31;
    const int mbase = blockIdx.x * 128;
    const int nblk  = blockIdx.y;
    const int kq    = blockIdx.z;
    const int b     = nblk >> 5;
    const int i0    = (nblk & 31) * 2;

    uint32_t mbR[3], mbF[3];
#pragma unroll
    for (int j = 0; j < 3; ++j) {
        mbR[j] = sb + MB_OFF + 8 * j;
        mbF[j] = sb + MB_OFF + 24 + 8 * j;
    }
    if (tid == 0) {
#pragma unroll
        for (int j = 0; j < 3; ++j) { MBINIT(mbR[j]); MBINIT(mbF[j]); }
    }
    __syncthreads();

    const int s0   = KQSTEPS * kq;
    const int tap0 = s0 >> 2;
    const int kc0  = s0 & 3;
    const int t0   = s0 / 20;
    const int r0   = s0 % 20;

    const int cA  = tid & 7;
    const int rA0 = tid >> 3;
    const uint32_t swc = 16u * (uint32_t)(cA ^ (rA0 & 7));
    const uint32_t adst = sb + (uint32_t)rA0 * 128 + swc;

    const __half* aptr = g_wq + (size_t)tap0 * 65536
                       + (size_t)(mbase + rA0) * 256 + (size_t)cA * 8
                       + (size_t)kc0 * 64;
    const __half* xptr = g_xq + (size_t)b * (HP * WP * 256)
                       + ((size_t)i0 * WP + rA0) * 256 + (size_t)cA * 8
                       + (size_t)t0 * 17408 + (size_t)r0 * 64;
    int ac4  = kc0;
    int xc20 = r0;

    const int mrow0 = (w >> 1) * 64;
    const int nrow0 = (w & 1) * 64;
    const uint32_t swz = (uint32_t)(l & 7);
    const uint32_t hl  = (uint32_t)(l >> 4);
    const uint32_t aLaneOff = (uint32_t)(mrow0 + (l & 15)) * 128;
    const uint32_t bLaneOff = (uint32_t)(nrow0 + (l & 7) + ((l >> 3) & 1) * 8) * 128;

    uint32_t aB[4], bB[4];
#pragma unroll
    for (int kh = 0; kh < 4; ++kh) {
        const uint32_t ch = 2u * kh + hl;
        aB[kh] = sb + aLaneOff + 16u * (ch ^ swz);
        bB[kh] = sb + OFF_B + bLaneOff + 16u * (ch ^ swz);
    }

    float acc[4][8][4];
#pragma unroll
    for (int mi = 0; mi < 4; ++mi)
#pragma unroll
        for (int nj = 0; nj < 8; ++nj)
#pragma unroll
            for (int r = 0; r < 4; ++r) acc[mi][nj][r] = 0.f;

    uint32_t bf0[4][4], bf1[4][4], ah0[4][4], ah1[4][4];

    auto issue = [&](const uint32_t so) {
#pragma unroll
        for (int k = 0; k < 8; ++k)
            cp16(so + adst + k * 2048, aptr + k * 4096);
#pragma unroll
        for (int k = 0; k < 8; ++k)
            cp16(so + adst + OFF_B + k * 2048,
                 xptr + (k >> 2) * 17408 + (k & 3) * 4096);
        aptr += (ac4 == 3) ? 65344 : 64;
        ac4 = (ac4 + 1) & 3;
        xptr += (xc20 == 19) ? 16192 : 64;
        xc20 = (xc20 == 19) ? 0 : xc20 + 1;
    };

    issue(0);              CPARRIVE(mbR[0]);
    issue(STAGE_STRIDE);   CPARRIVE(mbR[1]);
    MBARRIVE(mbF[2]);

    for (int i = 0; i < 91; ++i) {
        const uint32_t p = (uint32_t)(i & 1);
        STEP_FULL(0,                0, 2, p);
        STEP_FULL(STAGE_STRIDE,     1, 0, p);
        STEP_FULL(2 * STAGE_STRIDE, 2, 1, p);
    }
    STEP_TAIL(0,            0, 1u);
    STEP_TAIL(STAGE_STRIDE, 1, 1u);

    float* dst;
    if      (kq == 0) dst = out;
    else if (kq == 1) dst = g_p1;
    else if (kq == 2) dst = g_p2;
    else              dst = g_p3;

    const int lg = l >> 2;
    const int lc = l & 3;
    const int orow = i0 + (w & 1);

#pragma unroll
    for (int mi = 0; mi < 4; ++mi) {
#pragma unroll
        for (int h = 0; h < 2; ++h) {
            const int m = mbase + mrow0 + mi * 16 + lg + h * 8;
            float* rowp = dst + (((size_t)(b * 256 + m)) * 64 + orow) * 64 + 2 * lc;
#pragma unroll
            for (int nj = 0; nj < 8; ++nj)
                reinterpret_cast<float2*>(rowp + nj * 8)[0] =
                    make_float2(acc[mi][nj][2 * h], acc[mi][nj][2 * h + 1]);
        }
    }
}

// ---------------- fused reduce + BN (one block per channel) ----------------
__global__ __launch_bounds__(256)
void reduce_bn_kernel(float* __restrict__ out,
                      const float* __restrict__ gamma,
                      const float* __restrict__ beta)
{
    __shared__ float ssum[8], ssq[8];
    __shared__ float s_scale, s_shift;
    const int c   = blockIdx.x;       // channel
    const int tid = threadIdx.x;

    float4* o4 = reinterpret_cast<float4*>(out);
    const float4* p1 = reinterpret_cast<const float4*>(g_p1);
    const float4* p2 = reinterpret_cast<const float4*>(g_p2);
    const float4* p3 = reinterpret_cast<const float4*>(g_p3);

    float s = 0.f, sq = 0.f;
#pragma unroll
    for (int b = 0; b < Bn; ++b) {
        const size_t base4 = (size_t)(b * 256 + c) * 1024;
#pragma unroll
        for (int k = 0; k < 4; ++k) {
            const size_t i4 = base4 + tid + k * 256;
            float4 a = o4[i4], q1 = p1[i4], q2 = p2[i4], q3 = p3[i4];
            float4 v;
            v.x = a.x + q1.x + q2.x + q3.x;
            v.y = a.y + q1.y + q2.y + q3.y;
            v.z = a.z + q1.z + q2.z + q3.z;
            v.w = a.w + q1.w + q2.w + q3.w;
            o4[i4] = v;
            s  += v.x + v.y + v.z + v.w;
            sq += v.x * v.x + v.y * v.y + v.z * v.z + v.w * v.w;
        }
    }
#pragma unroll
    for (int o = 16; o > 0; o >>= 1) {
        s  += __shfl_xor_sync(0xffffffffu, s,  o);
        sq += __shfl_xor_sync(0xffffffffu, sq, o);
    }
    if ((tid & 31) == 0) { ssum[tid >> 5] = s; ssq[tid >> 5] = sq; }
    __syncthreads();
    if (tid == 0) {
        float ts = 0.f, tq = 0.f;
#pragma unroll
        for (int k = 0; k < 8; ++k) { ts += ssum[k]; tq += ssq[k]; }
        const float invN = 1.0f / (float)(Bn * Hdim * Wdim);
        float mean  = ts * invN;
        float var   = tq * invN - mean * mean;
        float scale = gamma[c] * rsqrtf(var + 1e-5f);
        s_scale = scale;
        s_shift = beta[c] - mean * scale;
    }
    __syncthreads();
    const float scale = s_scale, shift = s_shift;
#pragma unroll
    for (int b = 0; b < Bn; ++b) {
        const size_t base4 = (size_t)(b * 256 + c) * 1024;
#pragma unroll
        for (int k = 0; k < 4; ++k) {
            const size_t i4 = base4 + tid + k * 256;
            float4 v = o4[i4];
            v.x = v.x * scale + shift;
            v.y = v.y * scale + shift;
            v.z = v.z * scale + shift;
            v.w = v.w * scale + shift;
            o4[i4] = v;
        }
    }
}

// ---------------- launch ----------------
extern "C" void kernel_launch(void* const* d_in, const int* in_sizes, int n_in,
                              void* d_out, int out_size)
{
    const float* x     = (const float*)d_in[0];
    const float* w     = (const float*)d_in[1];
    const float* gamma = (const float*)d_in[2];
    const float* beta  = (const float*)d_in[3];
    float* out = (float*)d_out;

    cudaFuncSetAttribute(gemm_kernel, cudaFuncAttributeMaxDynamicSharedMemorySize,
                         SMEM_TOTAL);

    prep_w_kernel<<<COUTc * 11, 256>>>(w);     // 2816 blocks
    prep_x_kernel<<<dim3(HP, Bn), 256>>>(x);   // 960 blocks

    dim3 grid(2, 256, 4);                      // 2048 CTAs
    gemm_kernel<<<grid, 128, SMEM_TOTAL>>>(out);

    reduce_bn_kernel<<<COUTc, 256>>>(out, gamma, beta);
}

// round 17
// speedup vs baseline: 11.1555x; 1.0145x over previous
#include <cuda_runtime.h>
#include <cuda_fp16.h>
#include <stdint.h>

// ---------------- problem constants ----------------
#define Bn    8
#define CINc  256
#define COUTc 256
#define Hdim  64
#define Wdim  64
#define HP    120
#define WP    68
#define NTAP  275
#define KQSTEPS 275    // 1100 total steps / 4 K-quarters

// ---------------- smem (gemm) ----------------
#define OFF_B        16384
#define STAGE_STRIDE 32768          // A 16KB + B 16KB
#define MB_OFF       98304          // 6 mbarriers (8B each)
#define SMEM_TOTAL   (MB_OFF + 64)  // ~96KB -> 2 CTAs/SM

// ---------------- device scratch ----------------
__device__ __align__(256) __half g_xq[(size_t)Bn * HP * WP * CINc];
__device__ __align__(256) __half g_wq[(size_t)NTAP * COUTc * CINc];
__device__ __align__(16) __half g_p1[(size_t)Bn * COUTc * Hdim * Wdim];
__device__ __align__(16) __half g_p2[(size_t)Bn * COUTc * Hdim * Wdim];
__device__ __align__(16) __half g_p3[(size_t)Bn * COUTc * Hdim * Wdim];
__device__ float g_sum[COUTc];
__device__ float g_sqsum[COUTc];

// ---------------- PTX helpers ----------------
__device__ __forceinline__ uint32_t smem_u32(const void* p) {
    uint32_t a;
    asm("{ .reg .u64 t; cvta.to.shared.u64 t, %1; cvt.u32.u64 %0, t; }"
        : "=r"(a) : "l"(p));
    return a;
}
__device__ __forceinline__ void cp16(uint32_t dst, const void* src) {
    asm volatile("cp.async.cg.shared.global [%0], [%1], 16;"
                 :: "r"(dst), "l"(src) : "memory");
}

// mbarrier ops (sm_80/90 generic)
#define MBINIT(addr) \
    asm volatile("mbarrier.init.shared.b64 [%0], 128;" :: "r"(addr) : "memory")
#define MBARRIVE(addr) \
    asm volatile("{ .reg .b64 t; mbarrier.arrive.shared.b64 t, [%0]; }" \
                 :: "r"(addr) : "memory")
#define CPARRIVE(addr) \
    asm volatile("cp.async.mbarrier.arrive.noinc.shared.b64 [%0];" \
                 :: "r"(addr) : "memory")
#define MWAIT(addr, par) do {                                                       \
    uint32_t _mb = (addr); uint32_t _pa = (par); uint32_t _done;                    \
    asm volatile("{ .reg .pred p;"                                                  \
        " mbarrier.try_wait.parity.acquire.cta.shared::cta.b64 p, [%1], %2;"        \
        " selp.b32 %0,1,0,p; }" : "=r"(_done) : "r"(_mb), "r"(_pa) : "memory");     \
    if (!_done) {                                                                    \
        asm volatile("{ .reg .pred P1;"                                             \
            " WL_%=:"                                                               \
            " mbarrier.try_wait.parity.acquire.cta.shared::cta.b64 P1, [%0], %1, 0x989680;" \
            " @P1 bra.uni WD_%=;"                                                   \
            " bra.uni WL_%=;"                                                       \
            " WD_%=: }" :: "r"(_mb), "r"(_pa) : "memory");                          \
    }                                                                                \
} while (0)

__device__ __forceinline__ void ldsm4(uint32_t& r0, uint32_t& r1,
                                      uint32_t& r2, uint32_t& r3, uint32_t a) {
    asm volatile("ldmatrix.sync.aligned.m8n8.x4.shared.b16 {%0,%1,%2,%3}, [%4];"
                 : "=r"(r0), "=r"(r1), "=r"(r2), "=r"(r3) : "r"(a));
}
__device__ __forceinline__ void mma16816(float& d0, float& d1, float& d2, float& d3,
                                         uint32_t a0, uint32_t a1, uint32_t a2, uint32_t a3,
                                         uint32_t b0, uint32_t b1) {
    asm volatile("mma.sync.aligned.m16n8k16.row.col.f32.f16.f16.f32 "
                 "{%0,%1,%2,%3},{%4,%5,%6,%7},{%8,%9},{%0,%1,%2,%3};"
                 : "+f"(d0), "+f"(d1), "+f"(d2), "+f"(d3)
                 : "r"(a0), "r"(a1), "r"(a2), "r"(a3), "r"(b0), "r"(b1));
}

// ---------------- prep kernels (coalesced smem-transpose) ----------------
__global__ __launch_bounds__(256)
void prep_w_kernel(const float* __restrict__ w) {
    __shared__ __half s[25][260];
    const int g  = blockIdx.x;        // co*11 + ik
    const int co = g / 11;
    const int ik = g - co * 11;
    const int tid = threadIdx.x;

    const float* src = w + (size_t)g * 6400;
#pragma unroll
    for (int e = tid; e < 6400; e += 256) {
        const int ci = e / 25;
        const int r  = e - ci * 25;
        s[r][ci] = __float2half(src[e]);
    }
    __syncthreads();

    __half* dstb = g_wq + (size_t)(ik * 25) * 65536 + (size_t)co * 256;
#pragma unroll
    for (int r = 0; r < 25; ++r)
        dstb[(size_t)r * 65536 + tid] = s[r][tid];
}

__global__ __launch_bounds__(256)
void prep_x_kernel(const float* __restrict__ x) {
    __shared__ __half s[64][260];
    const int hp  = blockIdx.x;
    const int b   = blockIdx.y;
    const int tid = threadIdx.x;
    const int h   = hp - 25;

    __half* plane = g_xq + (size_t)(b * HP + hp) * (WP * 256);

    if ((unsigned)h >= 64u) {
        for (int j = tid; j < WP * 256; j += 256)
            plane[j] = __float2half(0.f);
        return;
    }

    const int wj  = tid & 63;
    const int cig = tid >> 6;
    const float* srcb = x + (size_t)b * (256 * 4096) + (size_t)h * 64;
#pragma unroll 4
    for (int cc = 0; cc < 64; ++cc) {
        const int ci = cc * 4 + cig;
        s[wj][ci] = __float2half(srcb[(size_t)ci * 4096 + wj]);
    }
    __syncthreads();

#pragma unroll 4
    for (int wp = 0; wp < WP; ++wp) {
        const int wq = wp - 2;
        __half v = ((unsigned)wq < 64u) ? s[wq][tid] : __float2half(0.f);
        plane[wp * 256 + tid] = v;
    }
}

__global__ void zero_stats_kernel() {
    int t = threadIdx.x;
    if (t < COUTc) { g_sum[t] = 0.f; g_sqsum[t] = 0.f; }
}

// ---- fragment load / mma macros ----
#define LDFRAGS(BF, AH, KH, SO) do {                                               \
    _Pragma("unroll")                                                              \
    for (int ni = 0; ni < 4; ++ni)                                                 \
        ldsm4(BF[ni][0], BF[ni][1], BF[ni][2], BF[ni][3],                          \
              bB[KH] + (SO) + ni * 2048);                                          \
    _Pragma("unroll")                                                              \
    for (int mi = 0; mi < 4; ++mi)                                                 \
        ldsm4(AH[mi][0], AH[mi][1], AH[mi][2], AH[mi][3],                          \
              aB[KH] + (SO) + mi * 2048);                                          \
} while (0)

#define MMAS(BF, AH) do {                                                          \
    _Pragma("unroll")                                                              \
    for (int mi = 0; mi < 4; ++mi)                                                 \
        _Pragma("unroll")                                                          \
        for (int ni = 0; ni < 4; ++ni) {                                           \
            mma16816(acc[mi][2*ni][0], acc[mi][2*ni][1],                           \
                     acc[mi][2*ni][2], acc[mi][2*ni][3],                           \
                     AH[mi][0], AH[mi][1], AH[mi][2], AH[mi][3],                   \
                     BF[ni][0], BF[ni][2]);                                        \
            mma16816(acc[mi][2*ni+1][0], acc[mi][2*ni+1][1],                       \
                     acc[mi][2*ni+1][2], acc[mi][2*ni+1][3],                       \
                     AH[mi][0], AH[mi][1], AH[mi][2], AH[mi][3],                   \
                     BF[ni][1], BF[ni][3]);                                        \
        }                                                                          \
} while (0)

#define STEP_FULL(SO, RJ, FJ, P) do {                                              \
    MWAIT(mbR[RJ], P);                                                             \
    LDFRAGS(bf0, ah0, 0, SO);                                                      \
    MWAIT(mbF[FJ], P);                                                             \
    issue((FJ) * STAGE_STRIDE);                                                    \
    CPARRIVE(mbR[FJ]);                                                             \
    LDFRAGS(bf1, ah1, 1, SO);                                                      \
    MMAS(bf0, ah0);                                                                \
    LDFRAGS(bf0, ah0, 2, SO);                                                      \
    MMAS(bf1, ah1);                                                                \
    LDFRAGS(bf1, ah1, 3, SO);                                                      \
    MBARRIVE(mbF[RJ]);                                                             \
    MMAS(bf0, ah0);                                                                \
    MMAS(bf1, ah1);                                                                \
} while (0)

#define STEP_TAIL(SO, RJ, P) do {                                                  \
    MWAIT(mbR[RJ], P);                                                             \
    LDFRAGS(bf0, ah0, 0, SO);                                                      \
    LDFRAGS(bf1, ah1, 1, SO);                                                      \
    MMAS(bf0, ah0);                                                                \
    LDFRAGS(bf0, ah0, 2, SO);                                                      \
    MMAS(bf1, ah1);                                                                \
    LDFRAGS(bf1, ah1, 3, SO);                                                      \
    MMAS(bf0, ah0);                                                                \
    MMAS(bf1, ah1);                                                                \
} while (0)

// ---------------- main GEMM kernel (mainloop identical to R14/R15) ----------------
__global__ __launch_bounds__(128, 2)
void gemm_kernel(float* __restrict__ out)
{
    extern __shared__ __align__(1024) char smem[];
    const uint32_t sb = smem_u32(smem);

    const int tid  = threadIdx.x;
    const int w    = tid >> 5;
    const int l    = tid & 31;
    const int mbase = blockIdx.x * 128;
    const int nblk  = blockIdx.y;
    const int kq    = blockIdx.z;
    const int b     = nblk >> 5;
    const int i0    = (nblk & 31) * 2;

    uint32_t mbR[3], mbF[3];
#pragma unroll
    for (int j = 0; j < 3; ++j) {
        mbR[j] = sb + MB_OFF + 8 * j;
        mbF[j] = sb + MB_OFF + 24 + 8 * j;
    }
    if (tid == 0) {
#pragma unroll
        for (int j = 0; j < 3; ++j) { MBINIT(mbR[j]); MBINIT(mbF[j]); }
    }
    __syncthreads();

    const int s0   = KQSTEPS * kq;
    const int tap0 = s0 >> 2;
    const int kc0  = s0 & 3;
    const int t0   = s0 / 20;
    const int r0   = s0 % 20;

    const int cA  = tid & 7;
    const int rA0 = tid >> 3;
    const uint32_t swc = 16u * (uint32_t)(cA ^ (rA0 & 7));
    const uint32_t adst = sb + (uint32_t)rA0 * 128 + swc;

    const __half* aptr = g_wq + (size_t)tap0 * 65536
                       + (size_t)(mbase + rA0) * 256 + (size_t)cA * 8
                       + (size_t)kc0 * 64;
    const __half* xptr = g_xq + (size_t)b * (HP * WP * 256)
                       + ((size_t)i0 * WP + rA0) * 256 + (size_t)cA * 8
                       + (size_t)t0 * 17408 + (size_t)r0 * 64;
    int ac4  = kc0;
    int xc20 = r0;

    const int mrow0 = (w >> 1) * 64;
    const int nrow0 = (w & 1) * 64;
    const uint32_t swz = (uint32_t)(l & 7);
    const uint32_t hl  = (uint32_t)(l >> 4);
    const uint32_t aLaneOff = (uint32_t)(mrow0 + (l & 15)) * 128;
    const uint32_t bLaneOff = (uint32_t)(nrow0 + (l & 7) + ((l >> 3) & 1) * 8) * 128;

    uint32_t aB[4], bB[4];
#pragma unroll
    for (int kh = 0; kh < 4; ++kh) {
        const uint32_t ch = 2u * kh + hl;
        aB[kh] = sb + aLaneOff + 16u * (ch ^ swz);
        bB[kh] = sb + OFF_B + bLaneOff + 16u * (ch ^ swz);
    }

    float acc[4][8][4];
#pragma unroll
    for (int mi = 0; mi < 4; ++mi)
#pragma unroll
        for (int nj = 0; nj < 8; ++nj)
#pragma unroll
            for (int r = 0; r < 4; ++r) acc[mi][nj][r] = 0.f;

    uint32_t bf0[4][4], bf1[4][4], ah0[4][4], ah1[4][4];

    auto issue = [&](const uint32_t so) {
#pragma unroll
        for (int k = 0; k < 8; ++k)
            cp16(so + adst + k * 2048, aptr + k * 4096);
#pragma unroll
        for (int k = 0; k < 8; ++k)
            cp16(so + adst + OFF_B + k * 2048,
                 xptr + (k >> 2) * 17408 + (k & 3) * 4096);
        aptr += (ac4 == 3) ? 65344 : 64;
        ac4 = (ac4 + 1) & 3;
        xptr += (xc20 == 19) ? 16192 : 64;
        xc20 = (xc20 == 19) ? 0 : xc20 + 1;
    };

    issue(0);              CPARRIVE(mbR[0]);
    issue(STAGE_STRIDE);   CPARRIVE(mbR[1]);
    MBARRIVE(mbF[2]);

    for (int i = 0; i < 91; ++i) {
        const uint32_t p = (uint32_t)(i & 1);
        STEP_FULL(0,                0, 2, p);
        STEP_FULL(STAGE_STRIDE,     1, 0, p);
        STEP_FULL(2 * STAGE_STRIDE, 2, 1, p);
    }
    STEP_TAIL(0,            0, 1u);
    STEP_TAIL(STAGE_STRIDE, 1, 1u);

    // ---- epilogue: kq0 -> fp32 out; kq1-3 -> fp16 partials ----
    const int lg = l >> 2;
    const int lc = l & 3;
    const int orow = i0 + (w & 1);

    if (kq == 0) {
#pragma unroll
        for (int mi = 0; mi < 4; ++mi) {
#pragma unroll
            for (int h = 0; h < 2; ++h) {
                const int m = mbase + mrow0 + mi * 16 + lg + h * 8;
                float* rowp = out + (((size_t)(b * 256 + m)) * 64 + orow) * 64 + 2 * lc;
#pragma unroll
                for (int nj = 0; nj < 8; ++nj)
                    reinterpret_cast<float2*>(rowp + nj * 8)[0] =
                        make_float2(acc[mi][nj][2 * h], acc[mi][nj][2 * h + 1]);
            }
        }
    } else {
        __half* dst = (kq == 1) ? g_p1 : (kq == 2) ? g_p2 : g_p3;
#pragma unroll
        for (int mi = 0; mi < 4; ++mi) {
#pragma unroll
            for (int h = 0; h < 2; ++h) {
                const int m = mbase + mrow0 + mi * 16 + lg + h * 8;
                __half* rowp = dst + (((size_t)(b * 256 + m)) * 64 + orow) * 64 + 2 * lc;
#pragma unroll
                for (int nj = 0; nj < 8; ++nj)
                    *reinterpret_cast<__half2*>(rowp + nj * 8) =
                        __floats2half2_rn(acc[mi][nj][2 * h], acc[mi][nj][2 * h + 1]);
            }
        }
    }
}

// ---------------- combine partials + stats (grid 256 x 8) ----------------
__global__ __launch_bounds__(256)
void combine_stats_kernel(float* __restrict__ out)
{
    __shared__ float ssum[8], ssq[8];
    const int c   = blockIdx.x;
    const int b   = blockIdx.y;
    const int tid = threadIdx.x;
    const size_t base4 = (size_t)(b * 256 + c) * 1024;

    float4* o4 = reinterpret_cast<float4*>(out);
    const __half2* p1 = reinterpret_cast<const __half2*>(g_p1);
    const __half2* p2 = reinterpret_cast<const __half2*>(g_p2);
    const __half2* p3 = reinterpret_cast<const __half2*>(g_p3);

    float s = 0.f, sq = 0.f;
#pragma unroll
    for (int k = 0; k < 4; ++k) {
        const size_t i4 = base4 + tid + k * 256;
        float4 v = o4[i4];
        float2 a0 = __half22float2(p1[2 * i4]);
        float2 a1 = __half22float2(p1[2 * i4 + 1]);
        float2 b0 = __half22float2(p2[2 * i4]);
        float2 b1 = __half22float2(p2[2 * i4 + 1]);
        float2 c0 = __half22float2(p3[2 * i4]);
        float2 c1 = __half22float2(p3[2 * i4 + 1]);
        v.x += a0.x + b0.x + c0.x;
        v.y += a0.y + b0.y + c0.y;
        v.z += a1.x + b1.x + c1.x;
        v.w += a1.y + b1.y + c1.y;
        o4[i4] = v;
        s  += v.x + v.y + v.z + v.w;
        sq += v.x * v.x + v.y * v.y + v.z * v.z + v.w * v.w;
    }
#pragma unroll
    for (int o = 16; o > 0; o >>= 1) {
        s  += __shfl_xor_sync(0xffffffffu, s,  o);
        sq += __shfl_xor_sync(0xffffffffu, sq, o);
    }
    if ((tid & 31) == 0) { ssum[tid >> 5] = s; ssq[tid >> 5] = sq; }
    __syncthreads();
    if (tid == 0) {
        float ts = 0.f, tq = 0.f;
#pragma unroll
        for (int k = 0; k < 8; ++k) { ts += ssum[k]; tq += ssq[k]; }
        atomicAdd(&g_sum[c], ts);
        atomicAdd(&g_sqsum[c], tq);
    }
}

// ---------------- BN normalize (grid 2048: one block per (b,c) image) ----------------
__global__ __launch_bounds__(256)
void bn_norm_kernel(float* __restrict__ out,
                    const float* __restrict__ gamma,
                    const float* __restrict__ beta)
{
    const int tid = threadIdx.x;
    const int c   = blockIdx.x & (COUTc - 1);   // blockIdx.x = b*256 + c
    const float invN = 1.0f / (float)(Bn * Hdim * Wdim);
    const float mean  = g_sum[c] * invN;
    const float var   = g_sqsum[c] * invN - mean * mean;
    const float scale = gamma[c] * rsqrtf(var + 1e-5f);
    const float shift = beta[c] - mean * scale;

    float4* o4 = reinterpret_cast<float4*>(out);
    const size_t base4 = (size_t)blockIdx.x * 1024;   // 1024 float4 per (b,c)
#pragma unroll
    for (int k = 0; k < 4; ++k) {
        const size_t i4 = base4 + tid + k * 256;
        float4 v = o4[i4];
        v.x = v.x * scale + shift;
        v.y = v.y * scale + shift;
        v.z = v.z * scale + shift;
        v.w = v.w * scale + shift;
        o4[i4] = v;
    }
}

// ---------------- launch ----------------
extern "C" void kernel_launch(void* const* d_in, const int* in_sizes, int n_in,
                              void* d_out, int out_size)
{
    const float* x     = (const float*)d_in[0];
    const float* w     = (const float*)d_in[1];
    const float* gamma = (const float*)d_in[2];
    const float* beta  = (const float*)d_in[3];
    float* out = (float*)d_out;

    cudaFuncSetAttribute(gemm_kernel, cudaFuncAttributeMaxDynamicSharedMemorySize,
                         SMEM_TOTAL);

    prep_w_kernel<<<COUTc * 11, 256>>>(w);
    prep_x_kernel<<<dim3(HP, Bn), 256>>>(x);
    zero_stats_kernel<<<1, 256>>>();

    dim3 grid(2, 256, 4);
    gemm_kernel<<<grid, 128, SMEM_TOTAL>>>(out);

    combine_stats_kernel<<<dim3(COUTc, Bn), 256>>>(out);       // 2048 blocks
    bn_norm_kernel<<<Bn * COUTc, 256>>>(out, gamma, beta);     // 2048 blocks
}